// round 11
// baseline (speedup 1.0000x reference)
#include <cuda_runtime.h>
#include <cuda_bf16.h>
#include <math.h>
#include <stdint.h>

#define BB  4
#define SS  1024
#define DD  1024
#define HH  16
#define HDm 64
#define MM  (BB*SS)      // 4096
#define DFF (4*DD)       // 4096
#define LNEPS 1e-5f

// ---------------- scratch ----------------------------------------------------
__device__ float g_x2 [(size_t)MM*DD];
__device__ float g_bqkv[3*DD];

// bf16 hi/lo buffers (uint4 => 16B aligned)
__device__ uint4 g_ahi [(size_t)MM*DD*2/16];   // h1 -> later ctx
__device__ uint4 g_alo [(size_t)MM*DD*2/16];
__device__ uint4 g_qhi [(size_t)MM*DD*2/16];   // q -> later h2
__device__ uint4 g_qlo [(size_t)MM*DD*2/16];
__device__ uint4 g_khi [(size_t)MM*DD*2/16];
__device__ uint4 g_klo [(size_t)MM*DD*2/16];
__device__ uint4 g_vhi [(size_t)MM*DD*2/16];
__device__ uint4 g_vlo [(size_t)MM*DD*2/16];
__device__ uint4 g_mhi [(size_t)MM*DFF*2/16];
__device__ uint4 g_mlo [(size_t)MM*DFF*2/16];
__device__ uint4 g_wqkvth[(size_t)3*DD*DD*2/16];
__device__ uint4 g_wqkvtl[(size_t)3*DD*DD*2/16];
__device__ uint4 g_woth[(size_t)DD*DD*2/16];
__device__ uint4 g_wotl[(size_t)DD*DD*2/16];
__device__ uint4 g_w1th[(size_t)DD*DFF*2/16];
__device__ uint4 g_w1tl[(size_t)DD*DFF*2/16];
__device__ uint4 g_w2th[(size_t)DFF*DD*2/16];
__device__ uint4 g_w2tl[(size_t)DFF*DD*2/16];

// ---------------- PTX helpers (sm_80+ baseline) ------------------------------
__device__ __forceinline__ uint32_t smem_to_u32(const void* p) {
    uint32_t a;
    asm("{ .reg .u64 t; cvta.to.shared.u64 t, %1; cvt.u32.u64 %0, t; }" : "=r"(a) : "l"(p));
    return a;
}
__device__ __forceinline__ void cp16(uint32_t dst, const void* src) {
    asm volatile("cp.async.cg.shared.global [%0], [%1], 16;" :: "r"(dst), "l"(src) : "memory");
}
__device__ __forceinline__ void ldsm4(uint32_t* r, uint32_t a) {
    asm volatile("ldmatrix.sync.aligned.m8n8.x4.shared.b16 {%0,%1,%2,%3}, [%4];"
        : "=r"(r[0]), "=r"(r[1]), "=r"(r[2]), "=r"(r[3]) : "r"(a));
}
__device__ __forceinline__ void ldsm4t(uint32_t* r, uint32_t a) {
    asm volatile("ldmatrix.sync.aligned.m8n8.x4.trans.shared.b16 {%0,%1,%2,%3}, [%4];"
        : "=r"(r[0]), "=r"(r[1]), "=r"(r[2]), "=r"(r[3]) : "r"(a));
}
__device__ __forceinline__ void mma16816(float* d, const uint32_t* a, const uint32_t* b) {
    asm volatile("mma.sync.aligned.m16n8k16.row.col.f32.bf16.bf16.f32 "
        "{%0,%1,%2,%3}, {%4,%5,%6,%7}, {%8,%9}, {%0,%1,%2,%3};"
        : "+f"(d[0]), "+f"(d[1]), "+f"(d[2]), "+f"(d[3])
        : "r"(a[0]), "r"(a[1]), "r"(a[2]), "r"(a[3]), "r"(b[0]), "r"(b[1]));
}
__device__ __forceinline__ void packhl(float x, float y, uint32_t& hi, uint32_t& lo) {
    __nv_bfloat16 hx = __float2bfloat16_rn(x), hy = __float2bfloat16_rn(y);
    __nv_bfloat16 lx = __float2bfloat16_rn(x - __bfloat162float(hx));
    __nv_bfloat16 ly = __float2bfloat16_rn(y - __bfloat162float(hy));
    __nv_bfloat162 h2 = __halves2bfloat162(hx, hy), l2 = __halves2bfloat162(lx, ly);
    hi = *(uint32_t*)&h2; lo = *(uint32_t*)&l2;
}

// ---------------- LayerNorm with vectorized hi/lo split output ---------------
__global__ __launch_bounds__(256) void ln_split_kernel(
    const float* __restrict__ x, const float* __restrict__ g,
    const float* __restrict__ b,
    __nv_bfloat16* __restrict__ ohi, __nv_bfloat16* __restrict__ olo)
{
    int row = blockIdx.x;
    int t = threadIdx.x;
    const float* xr = x + (size_t)row * DD;
    float4 v = *(const float4*)(xr + 4*t);
    float s = v.x + v.y + v.z + v.w;

    __shared__ float warpsum[8];
    __shared__ float s_mean, s_inv;
    int lane = t & 31, wid = t >> 5;
#pragma unroll
    for (int o = 16; o > 0; o >>= 1) s += __shfl_xor_sync(~0u, s, o);
    if (lane == 0) warpsum[wid] = s;
    __syncthreads();
    if (t == 0) {
        float tot = 0.f;
#pragma unroll
        for (int i = 0; i < 8; i++) tot += warpsum[i];
        s_mean = tot * (1.f/DD);
    }
    __syncthreads();
    float mean = s_mean;
    float d0 = v.x-mean, d1 = v.y-mean, d2 = v.z-mean, d3 = v.w-mean;
    float ss = d0*d0 + d1*d1 + d2*d2 + d3*d3;
#pragma unroll
    for (int o = 16; o > 0; o >>= 1) ss += __shfl_xor_sync(~0u, ss, o);
    if (lane == 0) warpsum[wid] = ss;
    __syncthreads();
    if (t == 0) {
        float tot = 0.f;
#pragma unroll
        for (int i = 0; i < 8; i++) tot += warpsum[i];
        s_inv = rsqrtf(tot * (1.f/DD) + LNEPS);
    }
    __syncthreads();
    float inv = s_inv;

    float4 gv = *(const float4*)(g + 4*t);
    float4 bv = *(const float4*)(b + 4*t);
    float o0 = d0 * inv * gv.x + bv.x;
    float o1 = d1 * inv * gv.y + bv.y;
    float o2 = d2 * inv * gv.z + bv.z;
    float o3 = d3 * inv * gv.w + bv.w;
    uint32_t h01, l01, h23, l23;
    packhl(o0, o1, h01, l01);
    packhl(o2, o3, h23, l23);
    uint2 hv; hv.x = h01; hv.y = h23;
    uint2 lv; lv.x = l01; lv.y = l23;
    *(uint2*)(ohi + (size_t)row*DD + 4*t) = hv;
    *(uint2*)(olo + (size_t)row*DD + 4*t) = lv;
}

// ---------------- bias concat -------------------------------------------------
__global__ void concat3_kernel(const float* __restrict__ a, const float* __restrict__ b,
                               const float* __restrict__ c, float* __restrict__ o)
{
    int i = blockIdx.x * 256 + threadIdx.x;
    if (i < DD) o[i] = a[i];
    else if (i < 2*DD) o[i] = b[i - DD];
    else o[i] = c[i - 2*DD];
}

// ---------------- weight transpose+split: W[K][N] -> Wt_hi/lo [N][K] ---------
__global__ __launch_bounds__(256) void transpose_split_kernel(
    const float* __restrict__ W, __nv_bfloat16* __restrict__ Thi,
    __nv_bfloat16* __restrict__ Tlo, int K, int N)
{
    __shared__ float tile[32][33];
    int n0 = blockIdx.x * 32, k0 = blockIdx.y * 32;
    int tx = threadIdx.x, ty = threadIdx.y;  // 32 x 8
#pragma unroll
    for (int r = 0; r < 4; r++)
        tile[ty + 8*r][tx] = W[(size_t)(k0 + ty + 8*r) * N + n0 + tx];
    __syncthreads();
#pragma unroll
    for (int r = 0; r < 4; r++) {
        int rr = ty + 8*r;
        float v = tile[tx][rr];
        __nv_bfloat16 h = __float2bfloat16_rn(v);
        __nv_bfloat16 l = __float2bfloat16_rn(v - __bfloat162float(h));
        size_t oi = (size_t)(n0 + rr) * K + k0 + tx;
        Thi[oi] = h; Tlo[oi] = l;
    }
}

// ---------------- warp-MMA split-bf16 GEMM (256x128 CTA tile) ----------------
// C = A @ B^T : A [M,K] hi/lo, B [N,K] hi/lo. 8 warps of 64x64 (4M x 2N).
// 2-stage cp.async pipeline, BK=64. SMEM/stage: Ahi|Alo (256x144) Bhi|Blo (128x144)
// MODE: 0 = fp32 out + residual; 2 = gelu + split hi/lo out; 3 = fused QKV route
#define ASUB   (256*144)             // 36864
#define BSUB   (128*144)             // 18432
#define STAGEB (2*ASUB + 2*BSUB)     // 110592
#define GSMEM_BYTES (2*STAGEB)       // 221184

__device__ __forceinline__ void ld_chunk(uint32_t s0, int tid,
    const char* a0, const char* a1, const char* b0, const char* b1,
    size_t strb, int kc)
{
    const char* abase[2] = { a0, a1 };
#pragma unroll
    for (int sub = 0; sub < 2; sub++) {
#pragma unroll
        for (int t = 0; t < 8; t++) {
            int seg = t*256 + tid;
            int r = seg >> 3, s = seg & 7;
            cp16(s0 + sub*ASUB + r*144 + s*16,
                 abase[sub] + (size_t)r * strb + (size_t)kc * 128 + s*16);
        }
    }
    const char* bbase[2] = { b0, b1 };
#pragma unroll
    for (int sub = 0; sub < 2; sub++) {
#pragma unroll
        for (int t = 0; t < 4; t++) {
            int seg = t*256 + tid;
            int r = seg >> 3, s = seg & 7;
            cp16(s0 + 2*ASUB + sub*BSUB + r*144 + s*16,
                 bbase[sub] + (size_t)r * strb + (size_t)kc * 128 + s*16);
        }
    }
    asm volatile("cp.async.commit_group;" ::: "memory");
}

template<int MODE>
__global__ __launch_bounds__(256) void gemm_mma(
    const __nv_bfloat16* __restrict__ Ahi, const __nv_bfloat16* __restrict__ Alo,
    const __nv_bfloat16* __restrict__ Bhi, const __nv_bfloat16* __restrict__ Blo,
    const float* __restrict__ bias, const float* __restrict__ res,
    float* __restrict__ C,
    __nv_bfloat16* __restrict__ O0h, __nv_bfloat16* __restrict__ O0l,
    __nv_bfloat16* __restrict__ O1h, __nv_bfloat16* __restrict__ O1l,
    __nv_bfloat16* __restrict__ O2h, __nv_bfloat16* __restrict__ O2l,
    int N, int K)
{
    extern __shared__ char smem[];
    uint32_t sb = smem_to_u32(smem);
    int tid = threadIdx.x, lane = tid & 31, wid = tid >> 5;
    int m0 = blockIdx.y * 256, n0 = blockIdx.x * 128;
    int wr = wid >> 1, wc = wid & 1;     // warp tile: rows wr*64, cols wc*64

    size_t strb = (size_t)K * 2;
    const char* a0 = (const char*)(Ahi + (size_t)m0 * K);
    const char* a1 = (const char*)(Alo + (size_t)m0 * K);
    const char* b0 = (const char*)(Bhi + (size_t)n0 * K);
    const char* b1 = (const char*)(Blo + (size_t)n0 * K);

    float acc[4][8][4];
#pragma unroll
    for (int i = 0; i < 4; i++)
#pragma unroll
        for (int j = 0; j < 8; j++)
#pragma unroll
            for (int r = 0; r < 4; r++) acc[i][j][r] = 0.f;

    int NC = K >> 6;
    ld_chunk(sb, tid, a0, a1, b0, b1, strb, 0);
    if (NC > 1) ld_chunk(sb + STAGEB, tid, a0, a1, b0, b1, strb, 1);

    for (int i = 0; i < NC; i++) {
        if (i + 1 < NC) { asm volatile("cp.async.wait_group 1;" ::: "memory"); }
        else            { asm volatile("cp.async.wait_group 0;" ::: "memory"); }
        __syncthreads();

        uint32_t st = sb + (i & 1)*STAGEB;
        uint32_t a_base = st + (wr*64 + (lane & 15))*144 + (lane >> 4)*16;
        uint32_t b_base = st + 2*ASUB +
            (wc*64 + (lane & 7) + ((lane >> 4) & 1)*8)*144 + ((lane >> 3) & 1)*16;

#pragma unroll
        for (int ks = 0; ks < 4; ks++) {
            uint32_t ah[4][4], al[4][4];
#pragma unroll
            for (int mi = 0; mi < 4; mi++) {
                uint32_t ad = a_base + mi*16*144 + ks*32;
                ldsm4(ah[mi], ad);
                ldsm4(al[mi], ad + ASUB);
            }
#pragma unroll
            for (int bp = 0; bp < 4; bp++) {
                uint32_t bh4[4], bl4[4];
                uint32_t bd = b_base + bp*16*144 + ks*32;
                ldsm4(bh4, bd);
                ldsm4(bl4, bd + BSUB);
#pragma unroll
                for (int mi = 0; mi < 4; mi++) {
#pragma unroll
                    for (int sub = 0; sub < 2; sub++) {
                        int nj = bp*2 + sub;
                        mma16816(acc[mi][nj], ah[mi], &bh4[sub*2]);
                        mma16816(acc[mi][nj], ah[mi], &bl4[sub*2]);
                        mma16816(acc[mi][nj], al[mi], &bh4[sub*2]);
                    }
                }
            }
        }
        __syncthreads();
        if (i + 2 < NC)
            ld_chunk(sb + (i & 1)*STAGEB, tid, a0, a1, b0, b1, strb, i + 2);
    }

    // ---- epilogue ----
    __nv_bfloat16 *oh = O0h, *ol = O0l;
    int lc0 = n0;
    float scale = 1.0f;
    if (MODE == 3) {
        int mat = n0 >> 10;
        lc0 = n0 & 1023;
        oh = (mat == 0) ? O0h : ((mat == 1) ? O1h : O2h);
        ol = (mat == 0) ? O0l : ((mat == 1) ? O1l : O2l);
        scale = (mat == 0) ? 0.125f : 1.0f;
    }

    float bx[8], by[8];
#pragma unroll
    for (int nj = 0; nj < 8; nj++) {
        int c = n0 + wc*64 + nj*8 + (lane & 3)*2;
        bx[nj] = bias[c]; by[nj] = bias[c+1];
    }
#pragma unroll
    for (int mi = 0; mi < 4; mi++) {
        int rbase = m0 + wr*64 + mi*16 + (lane >> 2);
#pragma unroll
        for (int half = 0; half < 2; half++) {
            int r = rbase + half*8;
#pragma unroll
            for (int nj = 0; nj < 8; nj++) {
                int cc = wc*64 + nj*8 + (lane & 3)*2;
                float v0 = acc[mi][nj][half*2+0] + bx[nj];
                float v1 = acc[mi][nj][half*2+1] + by[nj];
                if (MODE == 2) {
                    v0 = 0.5f * v0 * (1.f + erff(v0 * 0.70710678118654752f));
                    v1 = 0.5f * v1 * (1.f + erff(v1 * 0.70710678118654752f));
                }
                if (MODE == 0) {
                    int c = n0 + cc;
                    float2 rv = *(const float2*)(res + (size_t)r * N + c);
                    float2 o; o.x = v0 + rv.x; o.y = v1 + rv.y;
                    *(float2*)(C + (size_t)r * N + c) = o;
                } else if (MODE == 2) {
                    uint32_t hi, lo;
                    packhl(v0, v1, hi, lo);
                    int c = n0 + cc;
                    *(uint32_t*)(oh + (size_t)r * N + c) = hi;
                    *(uint32_t*)(ol + (size_t)r * N + c) = lo;
                } else { // MODE 3
                    v0 *= scale; v1 *= scale;
                    uint32_t hi, lo;
                    packhl(v0, v1, hi, lo);
                    int c = lc0 + cc;
                    *(uint32_t*)(oh + (size_t)r * DD + c) = hi;
                    *(uint32_t*)(ol + (size_t)r * DD + c) = lo;
                }
            }
        }
    }
}

// ---------------- fused flash attention (double-buffered K/V) ----------------
// grid (SS/128, BB*HH), 256 threads (8 warps x 16 q-rows).
#define FQH 0
#define FQL 18432
#define FKV 36864
#define FSTG 73728                    // KH|KL|VH|VL per stage
#define FSMEM (36864 + 2*73728)       // 184320

__device__ __forceinline__ void fl_load_tile(uint32_t dst, int tid, const char* g)
{
#pragma unroll
    for (int t = 0; t < 4; t++) {
        int seg = t*256 + tid;
        int r = seg >> 3, s = seg & 7;
        cp16(dst + r*144 + s*16, g + (size_t)r * (DD*2) + s*16);
    }
}

__global__ __launch_bounds__(256) void flash_kernel(
    const __nv_bfloat16* __restrict__ qhi, const __nv_bfloat16* __restrict__ qlo,
    const __nv_bfloat16* __restrict__ khi, const __nv_bfloat16* __restrict__ klo,
    const __nv_bfloat16* __restrict__ vhi, const __nv_bfloat16* __restrict__ vlo,
    __nv_bfloat16* __restrict__ chi, __nv_bfloat16* __restrict__ clo)
{
    extern __shared__ char smem[];
    uint32_t sb = smem_to_u32(smem);
    int tid = threadIdx.x, lane = tid & 31, w = tid >> 5;
    int q0 = blockIdx.x * 128;
    int bh = blockIdx.y, b = bh >> 4, h = bh & 15;

    size_t qoff = ((size_t)(b*SS + q0) * DD + h*HDm) * 2;
    size_t koff = ((size_t)(b*SS) * DD + h*HDm) * 2;

    // group 0: Q + KV(0) ; group 1: KV(1)
    fl_load_tile(sb + FQH, tid, (const char*)qhi + qoff);
    fl_load_tile(sb + FQL, tid, (const char*)qlo + qoff);
    fl_load_tile(sb + FKV +     0, tid, (const char*)khi + koff);
    fl_load_tile(sb + FKV + 18432, tid, (const char*)klo + koff);
    fl_load_tile(sb + FKV + 36864, tid, (const char*)vhi + koff);
    fl_load_tile(sb + FKV + 55296, tid, (const char*)vlo + koff);
    asm volatile("cp.async.commit_group;" ::: "memory");
    {
        size_t off = koff + (size_t)128 * DD * 2;
        fl_load_tile(sb + FKV + FSTG +     0, tid, (const char*)khi + off);
        fl_load_tile(sb + FKV + FSTG + 18432, tid, (const char*)klo + off);
        fl_load_tile(sb + FKV + FSTG + 36864, tid, (const char*)vhi + off);
        fl_load_tile(sb + FKV + FSTG + 55296, tid, (const char*)vlo + off);
        asm volatile("cp.async.commit_group;" ::: "memory");
    }

    float oacc[8][4];
#pragma unroll
    for (int i = 0; i < 8; i++)
#pragma unroll
        for (int r = 0; r < 4; r++) oacc[i][r] = 0.f;
    float mrow[2] = { -1e30f, -1e30f };
    float lrow[2] = { 0.f, 0.f };

    uint32_t a_base = sb + FQH + (w*16 + (lane & 15))*144 + (lane >> 4)*16;

    for (int j = 0; j < SS/128; j++) {
        if (j < SS/128 - 1) { asm volatile("cp.async.wait_group 1;" ::: "memory"); }
        else                { asm volatile("cp.async.wait_group 0;" ::: "memory"); }
        __syncthreads();

        uint32_t kb = sb + FKV + (j & 1)*FSTG;

        float sacc[16][4];
#pragma unroll
        for (int i = 0; i < 16; i++)
#pragma unroll
            for (int r = 0; r < 4; r++) sacc[i][r] = 0.f;

#pragma unroll
        for (int ks = 0; ks < 4; ks++) {
            uint32_t ah[4], al[4];
            ldsm4(ah, a_base + ks*32);
            ldsm4(al, a_base + FQL + ks*32);
#pragma unroll
            for (int nt = 0; nt < 8; nt++) {
                uint32_t bh4[4], bl4[4];
                uint32_t bd = kb + (nt*16 + (lane & 7) + ((lane >> 4) & 1)*8)*144
                            + ((lane >> 3) & 1)*16 + ks*32;
                ldsm4(bh4, bd);
                ldsm4(bl4, bd + 18432);
#pragma unroll
                for (int half = 0; half < 2; half++) {
                    mma16816(sacc[2*nt+half], ah, &bh4[half*2]);
                    mma16816(sacc[2*nt+half], ah, &bl4[half*2]);
                    mma16816(sacc[2*nt+half], al, &bh4[half*2]);
                }
            }
        }

#pragma unroll
        for (int half = 0; half < 2; half++) {
            float mx = -1e30f;
#pragma unroll
            for (int nt = 0; nt < 16; nt++) {
                mx = fmaxf(mx, sacc[nt][half*2+0]);
                mx = fmaxf(mx, sacc[nt][half*2+1]);
            }
            mx = fmaxf(mx, __shfl_xor_sync(~0u, mx, 1));
            mx = fmaxf(mx, __shfl_xor_sync(~0u, mx, 2));
            float mnew = fmaxf(mrow[half], mx);
            float alpha = __expf(mrow[half] - mnew);
            mrow[half] = mnew;
            float sum = 0.f;
#pragma unroll
            for (int nt = 0; nt < 16; nt++) {
                float p0 = __expf(sacc[nt][half*2+0] - mnew);
                float p1 = __expf(sacc[nt][half*2+1] - mnew);
                sacc[nt][half*2+0] = p0; sacc[nt][half*2+1] = p1;
                sum += p0 + p1;
            }
            lrow[half] = lrow[half] * alpha + sum;
#pragma unroll
            for (int on = 0; on < 8; on++) {
                oacc[on][half*2+0] *= alpha;
                oacc[on][half*2+1] *= alpha;
            }
        }

#pragma unroll
        for (int kt = 0; kt < 8; kt++) {
            uint32_t phi[4], plo[4];
            packhl(sacc[2*kt  ][0], sacc[2*kt  ][1], phi[0], plo[0]);
            packhl(sacc[2*kt  ][2], sacc[2*kt  ][3], phi[1], plo[1]);
            packhl(sacc[2*kt+1][0], sacc[2*kt+1][1], phi[2], plo[2]);
            packhl(sacc[2*kt+1][2], sacc[2*kt+1][3], phi[3], plo[3]);
#pragma unroll
            for (int np = 0; np < 4; np++) {
                uint32_t vh4[4], vl4[4];
                uint32_t vd = kb + 36864 + (16*kt + (lane & 15))*144
                            + (np*16 + (lane >> 4)*8)*2;
                ldsm4t(vh4, vd);
                ldsm4t(vl4, vd + 18432);
#pragma unroll
                for (int half = 0; half < 2; half++) {
                    mma16816(oacc[2*np+half], phi, &vh4[half*2]);
                    mma16816(oacc[2*np+half], phi, &vl4[half*2]);
                    mma16816(oacc[2*np+half], plo, &vh4[half*2]);
                }
            }
        }

        __syncthreads();
        if (j + 2 < SS/128) {
            size_t off = koff + (size_t)(j+2) * 128 * DD * 2;
            uint32_t dst = sb + FKV + (j & 1)*FSTG;
            fl_load_tile(dst +     0, tid, (const char*)khi + off);
            fl_load_tile(dst + 18432, tid, (const char*)klo + off);
            fl_load_tile(dst + 36864, tid, (const char*)vhi + off);
            fl_load_tile(dst + 55296, tid, (const char*)vlo + off);
            asm volatile("cp.async.commit_group;" ::: "memory");
        }
    }

#pragma unroll
    for (int half = 0; half < 2; half++) {
        float l = lrow[half];
        l += __shfl_xor_sync(~0u, l, 1);
        l += __shfl_xor_sync(~0u, l, 2);
        float inv = 1.f / l;
        int r = b*SS + q0 + w*16 + (lane >> 2) + half*8;
#pragma unroll
        for (int on = 0; on < 8; on++) {
            int c = h*HDm + on*8 + (lane & 3)*2;
            float v0 = oacc[on][half*2+0] * inv;
            float v1 = oacc[on][half*2+1] * inv;
            uint32_t hi, lo;
            packhl(v0, v1, hi, lo);
            *(uint32_t*)(chi + (size_t)r * DD + c) = hi;
            *(uint32_t*)(clo + (size_t)r * DD + c) = lo;
        }
    }
}

// ---------------- launch ------------------------------------------------------
extern "C" void kernel_launch(void* const* d_in, const int* in_sizes, int n_in,
                              void* d_out, int out_size)
{
    const float* x    = (const float*)d_in[0];
    const float* ln1g = (const float*)d_in[1];
    const float* ln1b = (const float*)d_in[2];
    const float* wq   = (const float*)d_in[3];
    const float* bq   = (const float*)d_in[4];
    const float* wk   = (const float*)d_in[5];
    const float* bk   = (const float*)d_in[6];
    const float* wv   = (const float*)d_in[7];
    const float* bv   = (const float*)d_in[8];
    const float* wo   = (const float*)d_in[9];
    const float* bo   = (const float*)d_in[10];
    const float* ln2g = (const float*)d_in[11];
    const float* ln2b = (const float*)d_in[12];
    const float* w1   = (const float*)d_in[13];
    const float* b1   = (const float*)d_in[14];
    const float* w2   = (const float*)d_in[15];
    const float* b2   = (const float*)d_in[16];
    float* out = (float*)d_out;

    float *x2, *bqkv;
    cudaGetSymbolAddress((void**)&x2, g_x2);
    cudaGetSymbolAddress((void**)&bqkv, g_bqkv);

    __nv_bfloat16 *ahi, *alo, *qhi, *qlo, *khi, *klo, *vhi, *vlo, *mhi, *mlo;
    __nv_bfloat16 *wqkvth, *wqkvtl, *woth, *wotl, *w1th, *w1tl, *w2th, *w2tl;
    cudaGetSymbolAddress((void**)&ahi,  g_ahi);
    cudaGetSymbolAddress((void**)&alo,  g_alo);
    cudaGetSymbolAddress((void**)&qhi,  g_qhi);
    cudaGetSymbolAddress((void**)&qlo,  g_qlo);
    cudaGetSymbolAddress((void**)&khi,  g_khi);
    cudaGetSymbolAddress((void**)&klo,  g_klo);
    cudaGetSymbolAddress((void**)&vhi,  g_vhi);
    cudaGetSymbolAddress((void**)&vlo,  g_vlo);
    cudaGetSymbolAddress((void**)&mhi,  g_mhi);
    cudaGetSymbolAddress((void**)&mlo,  g_mlo);
    cudaGetSymbolAddress((void**)&wqkvth, g_wqkvth);
    cudaGetSymbolAddress((void**)&wqkvtl, g_wqkvtl);
    cudaGetSymbolAddress((void**)&woth, g_woth);
    cudaGetSymbolAddress((void**)&wotl, g_wotl);
    cudaGetSymbolAddress((void**)&w1th, g_w1th);
    cudaGetSymbolAddress((void**)&w1tl, g_w1tl);
    cudaGetSymbolAddress((void**)&w2th, g_w2th);
    cudaGetSymbolAddress((void**)&w2tl, g_w2tl);

    cudaFuncSetAttribute(gemm_mma<0>, cudaFuncAttributeMaxDynamicSharedMemorySize, GSMEM_BYTES);
    cudaFuncSetAttribute(gemm_mma<2>, cudaFuncAttributeMaxDynamicSharedMemorySize, GSMEM_BYTES);
    cudaFuncSetAttribute(gemm_mma<3>, cudaFuncAttributeMaxDynamicSharedMemorySize, GSMEM_BYTES);
    cudaFuncSetAttribute(flash_kernel, cudaFuncAttributeMaxDynamicSharedMemorySize, FSMEM);

    dim3 tb(32, 8);

    // launches 0-4: QKV weight prep + LN  (so launch #5 = fused QKV GEMM, the
    // one ncu's "-s 5 -c 1" window captures)
    transpose_split_kernel<<<dim3(DD/32,  DD/32),  tb>>>(wq, wqkvth,                  wqkvtl,                  DD, DD);
    transpose_split_kernel<<<dim3(DD/32,  DD/32),  tb>>>(wk, wqkvth + (size_t)DD*DD,  wqkvtl + (size_t)DD*DD,  DD, DD);
    transpose_split_kernel<<<dim3(DD/32,  DD/32),  tb>>>(wv, wqkvth + (size_t)2*DD*DD, wqkvtl + (size_t)2*DD*DD, DD, DD);
    concat3_kernel<<<12, 256>>>(bq, bk, bv, bqkv);
    ln_split_kernel<<<MM, 256>>>(x, ln1g, ln1b, ahi, alo);

    // 5: fused QKV projection -> q/k/v hi/lo (Q pre-scaled by 1/8)
    dim3 gqkv(3*DD/128, MM/256);
    gemm_mma<3><<<gqkv, 256, GSMEM_BYTES>>>(ahi, alo, wqkvth, wqkvtl, bqkv, nullptr,
        nullptr, qhi, qlo, khi, klo, vhi, vlo, 3*DD, DD);

    // remaining weight prep (needed later, overlaps nothing but order is free)
    transpose_split_kernel<<<dim3(DD/32,  DD/32),  tb>>>(wo, woth, wotl, DD,  DD);
    transpose_split_kernel<<<dim3(DFF/32, DD/32),  tb>>>(w1, w1th, w1tl, DD,  DFF);
    transpose_split_kernel<<<dim3(DD/32,  DFF/32), tb>>>(w2, w2th, w2tl, DFF, DD);

    // fused flash attention -> ctx hi/lo (reuse ahi/alo)
    flash_kernel<<<dim3(SS/128, BB*HH), 256, FSMEM>>>(
        qhi, qlo, khi, klo, vhi, vlo, ahi, alo);

    // x2 = x + ctx @ wo + bo  (fp32 out)
    dim3 g1(DD/128, MM/256);
    gemm_mma<0><<<g1, 256, GSMEM_BYTES>>>(ahi, alo, woth, wotl, bo, x,
        x2, nullptr, nullptr, nullptr, nullptr, nullptr, nullptr, DD, DD);

    // h2 = LN(x2) -> hi/lo (reuse qhi/qlo)
    ln_split_kernel<<<MM, 256>>>(x2, ln2g, ln2b, qhi, qlo);

    // mlp = gelu(h2 @ w1 + b1) -> hi/lo
    dim3 g2(DFF/128, MM/256);
    gemm_mma<2><<<g2, 256, GSMEM_BYTES>>>(qhi, qlo, w1th, w1tl, b1, nullptr,
        nullptr, mhi, mlo, nullptr, nullptr, nullptr, nullptr, DFF, DD);

    // out = x2 + mlp @ w2 + b2
    gemm_mma<0><<<g1, 256, GSMEM_BYTES>>>(mhi, mlo, w2th, w2tl, b2, x2,
        out, nullptr, nullptr, nullptr, nullptr, nullptr, nullptr, DD, DFF);
}

// round 13
// speedup vs baseline: 1.0422x; 1.0422x over previous
#include <cuda_runtime.h>
#include <cuda_bf16.h>
#include <math.h>
#include <stdint.h>

#define BB  4
#define SS  1024
#define DD  1024
#define HH  16
#define HDm 64
#define MM  (BB*SS)      // 4096
#define DFF (4*DD)       // 4096
#define LNEPS 1e-5f

// ---------------- scratch ----------------------------------------------------
__device__ float g_x2 [(size_t)MM*DD];
__device__ float g_bqkv[3*DD];

// bf16 hi/lo buffers (uint4 => 16B aligned)
__device__ uint4 g_ahi [(size_t)MM*DD*2/16];   // h1 -> later ctx
__device__ uint4 g_alo [(size_t)MM*DD*2/16];
__device__ uint4 g_qhi [(size_t)MM*DD*2/16];   // q -> later h2
__device__ uint4 g_qlo [(size_t)MM*DD*2/16];
__device__ uint4 g_khi [(size_t)MM*DD*2/16];
__device__ uint4 g_klo [(size_t)MM*DD*2/16];
__device__ uint4 g_vhi [(size_t)MM*DD*2/16];
__device__ uint4 g_vlo [(size_t)MM*DD*2/16];
__device__ uint4 g_mhi [(size_t)MM*DFF*2/16];
__device__ uint4 g_mlo [(size_t)MM*DFF*2/16];
__device__ uint4 g_wqkvth[(size_t)3*DD*DD*2/16];
__device__ uint4 g_wqkvtl[(size_t)3*DD*DD*2/16];
__device__ uint4 g_woth[(size_t)DD*DD*2/16];
__device__ uint4 g_wotl[(size_t)DD*DD*2/16];
__device__ uint4 g_w1th[(size_t)DD*DFF*2/16];
__device__ uint4 g_w1tl[(size_t)DD*DFF*2/16];
__device__ uint4 g_w2th[(size_t)DFF*DD*2/16];
__device__ uint4 g_w2tl[(size_t)DFF*DD*2/16];

// ---------------- PTX helpers (sm_80+ baseline) ------------------------------
__device__ __forceinline__ uint32_t smem_to_u32(const void* p) {
    uint32_t a;
    asm("{ .reg .u64 t; cvta.to.shared.u64 t, %1; cvt.u32.u64 %0, t; }" : "=r"(a) : "l"(p));
    return a;
}
__device__ __forceinline__ void cp16(uint32_t dst, const void* src) {
    asm volatile("cp.async.cg.shared.global [%0], [%1], 16;" :: "r"(dst), "l"(src) : "memory");
}
__device__ __forceinline__ void ldsm4(uint32_t* r, uint32_t a) {
    asm volatile("ldmatrix.sync.aligned.m8n8.x4.shared.b16 {%0,%1,%2,%3}, [%4];"
        : "=r"(r[0]), "=r"(r[1]), "=r"(r[2]), "=r"(r[3]) : "r"(a));
}
__device__ __forceinline__ void ldsm4t(uint32_t* r, uint32_t a) {
    asm volatile("ldmatrix.sync.aligned.m8n8.x4.trans.shared.b16 {%0,%1,%2,%3}, [%4];"
        : "=r"(r[0]), "=r"(r[1]), "=r"(r[2]), "=r"(r[3]) : "r"(a));
}
__device__ __forceinline__ void mma16816(float* d, const uint32_t* a, const uint32_t* b) {
    asm volatile("mma.sync.aligned.m16n8k16.row.col.f32.bf16.bf16.f32 "
        "{%0,%1,%2,%3}, {%4,%5,%6,%7}, {%8,%9}, {%0,%1,%2,%3};"
        : "+f"(d[0]), "+f"(d[1]), "+f"(d[2]), "+f"(d[3])
        : "r"(a[0]), "r"(a[1]), "r"(a[2]), "r"(a[3]), "r"(b[0]), "r"(b[1]));
}
__device__ __forceinline__ void packhl(float x, float y, uint32_t& hi, uint32_t& lo) {
    __nv_bfloat16 hx = __float2bfloat16_rn(x), hy = __float2bfloat16_rn(y);
    __nv_bfloat16 lx = __float2bfloat16_rn(x - __bfloat162float(hx));
    __nv_bfloat16 ly = __float2bfloat16_rn(y - __bfloat162float(hy));
    __nv_bfloat162 h2 = __halves2bfloat162(hx, hy), l2 = __halves2bfloat162(lx, ly);
    hi = *(uint32_t*)&h2; lo = *(uint32_t*)&l2;
}

// ---------------- LayerNorm with vectorized hi/lo split output ---------------
__global__ __launch_bounds__(256) void ln_split_kernel(
    const float* __restrict__ x, const float* __restrict__ g,
    const float* __restrict__ b,
    __nv_bfloat16* __restrict__ ohi, __nv_bfloat16* __restrict__ olo)
{
    int row = blockIdx.x;
    int t = threadIdx.x;
    const float* xr = x + (size_t)row * DD;
    float4 v = *(const float4*)(xr + 4*t);
    float s = v.x + v.y + v.z + v.w;

    __shared__ float warpsum[8];
    __shared__ float s_mean, s_inv;
    int lane = t & 31, wid = t >> 5;
#pragma unroll
    for (int o = 16; o > 0; o >>= 1) s += __shfl_xor_sync(~0u, s, o);
    if (lane == 0) warpsum[wid] = s;
    __syncthreads();
    if (t == 0) {
        float tot = 0.f;
#pragma unroll
        for (int i = 0; i < 8; i++) tot += warpsum[i];
        s_mean = tot * (1.f/DD);
    }
    __syncthreads();
    float mean = s_mean;
    float d0 = v.x-mean, d1 = v.y-mean, d2 = v.z-mean, d3 = v.w-mean;
    float ss = d0*d0 + d1*d1 + d2*d2 + d3*d3;
#pragma unroll
    for (int o = 16; o > 0; o >>= 1) ss += __shfl_xor_sync(~0u, ss, o);
    if (lane == 0) warpsum[wid] = ss;
    __syncthreads();
    if (t == 0) {
        float tot = 0.f;
#pragma unroll
        for (int i = 0; i < 8; i++) tot += warpsum[i];
        s_inv = rsqrtf(tot * (1.f/DD) + LNEPS);
    }
    __syncthreads();
    float inv = s_inv;

    float4 gv = *(const float4*)(g + 4*t);
    float4 bv = *(const float4*)(b + 4*t);
    float o0 = d0 * inv * gv.x + bv.x;
    float o1 = d1 * inv * gv.y + bv.y;
    float o2 = d2 * inv * gv.z + bv.z;
    float o3 = d3 * inv * gv.w + bv.w;
    uint32_t h01, l01, h23, l23;
    packhl(o0, o1, h01, l01);
    packhl(o2, o3, h23, l23);
    uint2 hv; hv.x = h01; hv.y = h23;
    uint2 lv; lv.x = l01; lv.y = l23;
    *(uint2*)(ohi + (size_t)row*DD + 4*t) = hv;
    *(uint2*)(olo + (size_t)row*DD + 4*t) = lv;
}

// ---------------- bias concat -------------------------------------------------
__global__ void concat3_kernel(const float* __restrict__ a, const float* __restrict__ b,
                               const float* __restrict__ c, float* __restrict__ o)
{
    int i = blockIdx.x * 256 + threadIdx.x;
    if (i < DD) o[i] = a[i];
    else if (i < 2*DD) o[i] = b[i - DD];
    else o[i] = c[i - 2*DD];
}

// ---------------- weight transpose+split: W[K][N] -> Wt_hi/lo [N][K] ---------
// 64(k) x 32(n) tiles; each thread packs a k-pair -> 4B coalesced stores
// (full 128B segment per warp on both hi and lo streams).
__global__ __launch_bounds__(256) void transpose_split_kernel(
    const float* __restrict__ W, __nv_bfloat16* __restrict__ Thi,
    __nv_bfloat16* __restrict__ Tlo, int K, int N)
{
    __shared__ float tile[64][33];
    int n0 = blockIdx.x * 32, k0 = blockIdx.y * 64;
    int tx = threadIdx.x, ty = threadIdx.y;  // 32 x 8
#pragma unroll
    for (int r = 0; r < 8; r++)
        tile[ty + 8*r][tx] = W[(size_t)(k0 + ty + 8*r) * N + n0 + tx];
    __syncthreads();
#pragma unroll
    for (int r = 0; r < 4; r++) {
        int nn = ty + 8*r;                     // 0..31
        float v0 = tile[2*tx  ][nn];
        float v1 = tile[2*tx+1][nn];
        uint32_t hi, lo;
        packhl(v0, v1, hi, lo);
        size_t oi = (size_t)(n0 + nn) * K + k0 + 2*tx;
        *(uint32_t*)(Thi + oi) = hi;
        *(uint32_t*)(Tlo + oi) = lo;
    }
}

// ---------------- warp-MMA split-bf16 GEMM (128x128, 3-stage — R10 proven) ---
// C = A @ B^T : A [M,K] hi/lo, B [N,K] hi/lo. 8 warps of 64x32.
// MODE: 0 = fp32 out + residual; 2 = gelu + split hi/lo out; 3 = fused QKV route
#define SUBB   (128*144)
#define STAGEB (4*SUBB)              // 73728 B
#define GSMEM_BYTES (3*STAGEB)       // 221184 B

__device__ __forceinline__ void ld_chunk(uint32_t s0, int tid,
    const char* a0, const char* a1, const char* b0, const char* b1,
    size_t strb, int kc)
{
    const char* bases[4] = { a0, a1, b0, b1 };
#pragma unroll
    for (int mtx = 0; mtx < 4; mtx++) {
        const char* base = bases[mtx];
#pragma unroll
        for (int t = 0; t < 4; t++) {
            int seg = t*256 + tid;
            int r = seg >> 3, s = seg & 7;
            cp16(s0 + mtx*SUBB + r*144 + s*16,
                 base + (size_t)r * strb + (size_t)kc * 128 + s*16);
        }
    }
    asm volatile("cp.async.commit_group;" ::: "memory");
}

template<int MODE>
__global__ __launch_bounds__(256) void gemm_mma(
    const __nv_bfloat16* __restrict__ Ahi, const __nv_bfloat16* __restrict__ Alo,
    const __nv_bfloat16* __restrict__ Bhi, const __nv_bfloat16* __restrict__ Blo,
    const float* __restrict__ bias, const float* __restrict__ res,
    float* __restrict__ C,
    __nv_bfloat16* __restrict__ O0h, __nv_bfloat16* __restrict__ O0l,
    __nv_bfloat16* __restrict__ O1h, __nv_bfloat16* __restrict__ O1l,
    __nv_bfloat16* __restrict__ O2h, __nv_bfloat16* __restrict__ O2l,
    int N, int K)
{
    extern __shared__ char smem[];
    uint32_t sb = smem_to_u32(smem);
    int tid = threadIdx.x, lane = tid & 31, wid = tid >> 5;
    int m0 = blockIdx.y * 128, n0 = blockIdx.x * 128;
    int wr = wid >> 2, wc = wid & 3;

    size_t strb = (size_t)K * 2;
    const char* a0 = (const char*)(Ahi + (size_t)m0 * K);
    const char* a1 = (const char*)(Alo + (size_t)m0 * K);
    const char* b0 = (const char*)(Bhi + (size_t)n0 * K);
    const char* b1 = (const char*)(Blo + (size_t)n0 * K);

    float acc[4][4][4];
#pragma unroll
    for (int i = 0; i < 4; i++)
#pragma unroll
        for (int j = 0; j < 4; j++)
#pragma unroll
            for (int r = 0; r < 4; r++) acc[i][j][r] = 0.f;

    int NC = K >> 6;
    ld_chunk(sb, tid, a0, a1, b0, b1, strb, 0);
    if (NC > 1) ld_chunk(sb + STAGEB, tid, a0, a1, b0, b1, strb, 1);

    int cs = 0, ns = 2;
    for (int i = 0; i < NC; i++) {
        if (i + 1 < NC) { asm volatile("cp.async.wait_group 1;" ::: "memory"); }
        else            { asm volatile("cp.async.wait_group 0;" ::: "memory"); }
        __syncthreads();

        uint32_t st = sb + cs*STAGEB;
        uint32_t a_base = st + (wr*64 + (lane & 15))*144 + (lane >> 4)*16;
        uint32_t b_base = st + 2*SUBB +
            (wc*32 + (lane & 7) + ((lane >> 4) & 1)*8)*144 + ((lane >> 3) & 1)*16;

#pragma unroll
        for (int ks = 0; ks < 4; ks++) {
            uint32_t ah[4][4], al[4][4], bh[2][4], bl[2][4];
#pragma unroll
            for (int mi = 0; mi < 4; mi++) {
                uint32_t ad = a_base + mi*16*144 + ks*32;
                ldsm4(ah[mi], ad);
                ldsm4(al[mi], ad + SUBB);
            }
#pragma unroll
            for (int bj = 0; bj < 2; bj++) {
                uint32_t bd = b_base + bj*16*144 + ks*32;
                ldsm4(bh[bj], bd);
                ldsm4(bl[bj], bd + SUBB);
            }
#pragma unroll
            for (int mi = 0; mi < 4; mi++) {
#pragma unroll
                for (int nj = 0; nj < 4; nj++) {
                    const uint32_t* bH = &bh[nj >> 1][(nj & 1)*2];
                    const uint32_t* bL = &bl[nj >> 1][(nj & 1)*2];
                    mma16816(acc[mi][nj], ah[mi], bH);
                    mma16816(acc[mi][nj], ah[mi], bL);
                    mma16816(acc[mi][nj], al[mi], bH);
                }
            }
        }

        if (i + 2 < NC)
            ld_chunk(sb + ns*STAGEB, tid, a0, a1, b0, b1, strb, i + 2);
        cs = (cs + 1 == 3) ? 0 : cs + 1;
        ns = (ns + 1 == 3) ? 0 : ns + 1;
    }

    // ---- epilogue ----
    __nv_bfloat16 *oh = O0h, *ol = O0l;
    int lc0 = n0;
    float scale = 1.0f;
    if (MODE == 3) {
        int mat = n0 >> 10;
        lc0 = n0 & 1023;
        oh = (mat == 0) ? O0h : ((mat == 1) ? O1h : O2h);
        ol = (mat == 0) ? O0l : ((mat == 1) ? O1l : O2l);
        scale = (mat == 0) ? 0.125f : 1.0f;
    }

    float bx[4], by[4];
#pragma unroll
    for (int nj = 0; nj < 4; nj++) {
        int c = n0 + wc*32 + nj*8 + (lane & 3)*2;
        bx[nj] = bias[c]; by[nj] = bias[c+1];
    }
#pragma unroll
    for (int mi = 0; mi < 4; mi++) {
        int rbase = m0 + wr*64 + mi*16 + (lane >> 2);
#pragma unroll
        for (int half = 0; half < 2; half++) {
            int r = rbase + half*8;
#pragma unroll
            for (int nj = 0; nj < 4; nj++) {
                int cc = wc*32 + nj*8 + (lane & 3)*2;
                float v0 = acc[mi][nj][half*2+0] + bx[nj];
                float v1 = acc[mi][nj][half*2+1] + by[nj];
                if (MODE == 2) {
                    v0 = 0.5f * v0 * (1.f + erff(v0 * 0.70710678118654752f));
                    v1 = 0.5f * v1 * (1.f + erff(v1 * 0.70710678118654752f));
                }
                if (MODE == 0) {
                    int c = n0 + cc;
                    float2 rv = *(const float2*)(res + (size_t)r * N + c);
                    float2 o; o.x = v0 + rv.x; o.y = v1 + rv.y;
                    *(float2*)(C + (size_t)r * N + c) = o;
                } else if (MODE == 2) {
                    uint32_t hi, lo;
                    packhl(v0, v1, hi, lo);
                    int c = n0 + cc;
                    *(uint32_t*)(oh + (size_t)r * N + c) = hi;
                    *(uint32_t*)(ol + (size_t)r * N + c) = lo;
                } else { // MODE 3
                    v0 *= scale; v1 *= scale;
                    uint32_t hi, lo;
                    packhl(v0, v1, hi, lo);
                    int c = lc0 + cc;
                    *(uint32_t*)(oh + (size_t)r * DD + c) = hi;
                    *(uint32_t*)(ol + (size_t)r * DD + c) = lo;
                }
            }
        }
    }
}

// ---------------- fused flash attention (R10 proven: 110.5KB, 2 CTA/SM) ------
#define FQH 0
#define FQL 18432
#define FKH 36864
#define FKL 55296
#define FVH 73728
#define FVL 92160
#define FSMEM 110592

__device__ __forceinline__ void fl_load_tile(uint32_t dst, int tid, const char* g)
{
#pragma unroll
    for (int t = 0; t < 4; t++) {
        int seg = t*256 + tid;
        int r = seg >> 3, s = seg & 7;
        cp16(dst + r*144 + s*16, g + (size_t)r * (DD*2) + s*16);
    }
}

__global__ __launch_bounds__(256) void flash_kernel(
    const __nv_bfloat16* __restrict__ qhi, const __nv_bfloat16* __restrict__ qlo,
    const __nv_bfloat16* __restrict__ khi, const __nv_bfloat16* __restrict__ klo,
    const __nv_bfloat16* __restrict__ vhi, const __nv_bfloat16* __restrict__ vlo,
    __nv_bfloat16* __restrict__ chi, __nv_bfloat16* __restrict__ clo)
{
    extern __shared__ char smem[];
    uint32_t sb = smem_to_u32(smem);
    int tid = threadIdx.x, lane = tid & 31, w = tid >> 5;
    int q0 = blockIdx.x * 128;
    int bh = blockIdx.y, b = bh >> 4, h = bh & 15;

    size_t qoff = ((size_t)(b*SS + q0) * DD + h*HDm) * 2;
    size_t koff = ((size_t)(b*SS) * DD + h*HDm) * 2;

    fl_load_tile(sb + FQH, tid, (const char*)qhi + qoff);
    fl_load_tile(sb + FQL, tid, (const char*)qlo + qoff);
    fl_load_tile(sb + FKH, tid, (const char*)khi + koff);
    fl_load_tile(sb + FKL, tid, (const char*)klo + koff);
    fl_load_tile(sb + FVH, tid, (const char*)vhi + koff);
    fl_load_tile(sb + FVL, tid, (const char*)vlo + koff);
    asm volatile("cp.async.commit_group;" ::: "memory");

    float oacc[8][4];
#pragma unroll
    for (int i = 0; i < 8; i++)
#pragma unroll
        for (int r = 0; r < 4; r++) oacc[i][r] = 0.f;
    float mrow[2] = { -1e30f, -1e30f };
    float lrow[2] = { 0.f, 0.f };

    uint32_t a_base = sb + FQH + (w*16 + (lane & 15))*144 + (lane >> 4)*16;

    for (int j = 0; j < SS/128; j++) {
        asm volatile("cp.async.wait_group 0;" ::: "memory");
        __syncthreads();

        float sacc[16][4];
#pragma unroll
        for (int i = 0; i < 16; i++)
#pragma unroll
            for (int r = 0; r < 4; r++) sacc[i][r] = 0.f;

#pragma unroll
        for (int ks = 0; ks < 4; ks++) {
            uint32_t ah[4], al[4];
            ldsm4(ah, a_base + ks*32);
            ldsm4(al, a_base + (FQL-FQH) + ks*32);
#pragma unroll
            for (int nt = 0; nt < 8; nt++) {
                uint32_t bh4[4], bl4[4];
                uint32_t bd = sb + FKH + (nt*16 + (lane & 7) + ((lane >> 4) & 1)*8)*144
                            + ((lane >> 3) & 1)*16 + ks*32;
                ldsm4(bh4, bd);
                ldsm4(bl4, bd + (FKL-FKH));
#pragma unroll
                for (int half = 0; half < 2; half++) {
                    mma16816(sacc[2*nt+half], ah, &bh4[half*2]);
                    mma16816(sacc[2*nt+half], ah, &bl4[half*2]);
                    mma16816(sacc[2*nt+half], al, &bh4[half*2]);
                }
            }
        }

#pragma unroll
        for (int half = 0; half < 2; half++) {
            float mx = -1e30f;
#pragma unroll
            for (int nt = 0; nt < 16; nt++) {
                mx = fmaxf(mx, sacc[nt][half*2+0]);
                mx = fmaxf(mx, sacc[nt][half*2+1]);
            }
            mx = fmaxf(mx, __shfl_xor_sync(~0u, mx, 1));
            mx = fmaxf(mx, __shfl_xor_sync(~0u, mx, 2));
            float mnew = fmaxf(mrow[half], mx);
            float alpha = __expf(mrow[half] - mnew);
            mrow[half] = mnew;
            float sum = 0.f;
#pragma unroll
            for (int nt = 0; nt < 16; nt++) {
                float p0 = __expf(sacc[nt][half*2+0] - mnew);
                float p1 = __expf(sacc[nt][half*2+1] - mnew);
                sacc[nt][half*2+0] = p0; sacc[nt][half*2+1] = p1;
                sum += p0 + p1;
            }
            lrow[half] = lrow[half] * alpha + sum;
#pragma unroll
            for (int on = 0; on < 8; on++) {
                oacc[on][half*2+0] *= alpha;
                oacc[on][half*2+1] *= alpha;
            }
        }

#pragma unroll
        for (int kt = 0; kt < 8; kt++) {
            uint32_t phi[4], plo[4];
            packhl(sacc[2*kt  ][0], sacc[2*kt  ][1], phi[0], plo[0]);
            packhl(sacc[2*kt  ][2], sacc[2*kt  ][3], phi[1], plo[1]);
            packhl(sacc[2*kt+1][0], sacc[2*kt+1][1], phi[2], plo[2]);
            packhl(sacc[2*kt+1][2], sacc[2*kt+1][3], phi[3], plo[3]);
#pragma unroll
            for (int np = 0; np < 4; np++) {
                uint32_t vh4[4], vl4[4];
                uint32_t vd = sb + FVH + (16*kt + (lane & 15))*144
                            + (np*16 + (lane >> 4)*8)*2;
                ldsm4t(vh4, vd);
                ldsm4t(vl4, vd + (FVL-FVH));
#pragma unroll
                for (int half = 0; half < 2; half++) {
                    mma16816(oacc[2*np+half], phi, &vh4[half*2]);
                    mma16816(oacc[2*np+half], phi, &vl4[half*2]);
                    mma16816(oacc[2*np+half], plo, &vh4[half*2]);
                }
            }
        }

        __syncthreads();
        if (j + 1 < SS/128) {
            size_t off = koff + (size_t)(j+1) * 128 * DD * 2;
            fl_load_tile(sb + FKH, tid, (const char*)khi + off);
            fl_load_tile(sb + FKL, tid, (const char*)klo + off);
            fl_load_tile(sb + FVH, tid, (const char*)vhi + off);
            fl_load_tile(sb + FVL, tid, (const char*)vlo + off);
            asm volatile("cp.async.commit_group;" ::: "memory");
        }
    }

#pragma unroll
    for (int half = 0; half < 2; half++) {
        float l = lrow[half];
        l += __shfl_xor_sync(~0u, l, 1);
        l += __shfl_xor_sync(~0u, l, 2);
        float inv = 1.f / l;
        int r = b*SS + q0 + w*16 + (lane >> 2) + half*8;
#pragma unroll
        for (int on = 0; on < 8; on++) {
            int c = h*HDm + on*8 + (lane & 3)*2;
            float v0 = oacc[on][half*2+0] * inv;
            float v1 = oacc[on][half*2+1] * inv;
            uint32_t hi, lo;
            packhl(v0, v1, hi, lo);
            *(uint32_t*)(chi + (size_t)r * DD + c) = hi;
            *(uint32_t*)(clo + (size_t)r * DD + c) = lo;
        }
    }
}

// ---------------- launch ------------------------------------------------------
extern "C" void kernel_launch(void* const* d_in, const int* in_sizes, int n_in,
                              void* d_out, int out_size)
{
    const float* x    = (const float*)d_in[0];
    const float* ln1g = (const float*)d_in[1];
    const float* ln1b = (const float*)d_in[2];
    const float* wq   = (const float*)d_in[3];
    const float* bq   = (const float*)d_in[4];
    const float* wk   = (const float*)d_in[5];
    const float* bk   = (const float*)d_in[6];
    const float* wv   = (const float*)d_in[7];
    const float* bv   = (const float*)d_in[8];
    const float* wo   = (const float*)d_in[9];
    const float* bo   = (const float*)d_in[10];
    const float* ln2g = (const float*)d_in[11];
    const float* ln2b = (const float*)d_in[12];
    const float* w1   = (const float*)d_in[13];
    const float* b1   = (const float*)d_in[14];
    const float* w2   = (const float*)d_in[15];
    const float* b2   = (const float*)d_in[16];
    float* out = (float*)d_out;

    float *x2, *bqkv;
    cudaGetSymbolAddress((void**)&x2, g_x2);
    cudaGetSymbolAddress((void**)&bqkv, g_bqkv);

    __nv_bfloat16 *ahi, *alo, *qhi, *qlo, *khi, *klo, *vhi, *vlo, *mhi, *mlo;
    __nv_bfloat16 *wqkvth, *wqkvtl, *woth, *wotl, *w1th, *w1tl, *w2th, *w2tl;
    cudaGetSymbolAddress((void**)&ahi,  g_ahi);
    cudaGetSymbolAddress((void**)&alo,  g_alo);
    cudaGetSymbolAddress((void**)&qhi,  g_qhi);
    cudaGetSymbolAddress((void**)&qlo,  g_qlo);
    cudaGetSymbolAddress((void**)&khi,  g_khi);
    cudaGetSymbolAddress((void**)&klo,  g_klo);
    cudaGetSymbolAddress((void**)&vhi,  g_vhi);
    cudaGetSymbolAddress((void**)&vlo,  g_vlo);
    cudaGetSymbolAddress((void**)&mhi,  g_mhi);
    cudaGetSymbolAddress((void**)&mlo,  g_mlo);
    cudaGetSymbolAddress((void**)&wqkvth, g_wqkvth);
    cudaGetSymbolAddress((void**)&wqkvtl, g_wqkvtl);
    cudaGetSymbolAddress((void**)&woth, g_woth);
    cudaGetSymbolAddress((void**)&wotl, g_wotl);
    cudaGetSymbolAddress((void**)&w1th, g_w1th);
    cudaGetSymbolAddress((void**)&w1tl, g_w1tl);
    cudaGetSymbolAddress((void**)&w2th, g_w2th);
    cudaGetSymbolAddress((void**)&w2tl, g_w2tl);

    cudaFuncSetAttribute(gemm_mma<0>, cudaFuncAttributeMaxDynamicSharedMemorySize, GSMEM_BYTES);
    cudaFuncSetAttribute(gemm_mma<2>, cudaFuncAttributeMaxDynamicSharedMemorySize, GSMEM_BYTES);
    cudaFuncSetAttribute(gemm_mma<3>, cudaFuncAttributeMaxDynamicSharedMemorySize, GSMEM_BYTES);
    cudaFuncSetAttribute(flash_kernel, cudaFuncAttributeMaxDynamicSharedMemorySize, FSMEM);

    dim3 tb(32, 8);

    // weight transpose+split (QKV concatenated into one [3072][1024] buffer)
    transpose_split_kernel<<<dim3(DD/32,  DD/64),  tb>>>(wq, wqkvth,                   wqkvtl,                   DD, DD);
    transpose_split_kernel<<<dim3(DD/32,  DD/64),  tb>>>(wk, wqkvth + (size_t)DD*DD,   wqkvtl + (size_t)DD*DD,   DD, DD);
    transpose_split_kernel<<<dim3(DD/32,  DD/64),  tb>>>(wv, wqkvth + (size_t)2*DD*DD, wqkvtl + (size_t)2*DD*DD, DD, DD);
    transpose_split_kernel<<<dim3(DD/32,  DD/64),  tb>>>(wo, woth, wotl, DD,  DD);
    transpose_split_kernel<<<dim3(DFF/32, DD/64),  tb>>>(w1, w1th, w1tl, DD,  DFF);
    transpose_split_kernel<<<dim3(DD/32,  DFF/64), tb>>>(w2, w2th, w2tl, DFF, DD);
    concat3_kernel<<<12, 256>>>(bq, bk, bv, bqkv);

    // 1. h1 = LN(x) -> hi/lo
    ln_split_kernel<<<MM, 256>>>(x, ln1g, ln1b, ahi, alo);

    // 2. fused QKV projection -> q/k/v hi/lo (Q pre-scaled by 1/8)
    dim3 gqkv(3*DD/128, MM/128);
    gemm_mma<3><<<gqkv, 256, GSMEM_BYTES>>>(ahi, alo, wqkvth, wqkvtl, bqkv, nullptr,
        nullptr, qhi, qlo, khi, klo, vhi, vlo, 3*DD, DD);

    // 3. fused flash attention -> ctx hi/lo (reuse ahi/alo)
    flash_kernel<<<dim3(SS/128, BB*HH), 256, FSMEM>>>(
        qhi, qlo, khi, klo, vhi, vlo, ahi, alo);

    // 4. x2 = x + ctx @ wo + bo  (fp32 out)
    dim3 g1(DD/128, MM/128);
    gemm_mma<0><<<g1, 256, GSMEM_BYTES>>>(ahi, alo, woth, wotl, bo, x,
        x2, nullptr, nullptr, nullptr, nullptr, nullptr, nullptr, DD, DD);

    // 5. h2 = LN(x2) -> hi/lo (reuse qhi/qlo)
    ln_split_kernel<<<MM, 256>>>(x2, ln2g, ln2b, qhi, qlo);

    // 6. mlp = gelu(h2 @ w1 + b1) -> hi/lo
    dim3 g2(DFF/128, MM/128);
    gemm_mma<2><<<g2, 256, GSMEM_BYTES>>>(qhi, qlo, w1th, w1tl, b1, nullptr,
        nullptr, mhi, mlo, nullptr, nullptr, nullptr, nullptr, DFF, DD);

    // 7. out = x2 + mlp @ w2 + b2
    gemm_mma<0><<<g1, 256, GSMEM_BYTES>>>(mhi, mlo, w2th, w2tl, b2, x2,
        out, nullptr, nullptr, nullptr, nullptr, nullptr, nullptr, DD, DFF);
}

// round 15
// speedup vs baseline: 1.0641x; 1.0210x over previous
#include <cuda_runtime.h>
#include <cuda_bf16.h>
#include <math.h>
#include <stdint.h>

#define BB  4
#define SS  1024
#define DD  1024
#define HH  16
#define HDm 64
#define MM  (BB*SS)      // 4096
#define DFF (4*DD)       // 4096
#define LNEPS 1e-5f

// ---------------- scratch ----------------------------------------------------
__device__ float g_x2 [(size_t)MM*DD];
__device__ float g_bqkv[3*DD];

// bf16 hi/lo buffers (uint4 => 16B aligned)
__device__ uint4 g_ahi [(size_t)MM*DD*2/16];   // h1 -> later ctx
__device__ uint4 g_alo [(size_t)MM*DD*2/16];
__device__ uint4 g_qhi [(size_t)MM*DD*2/16];   // q -> later h2
__device__ uint4 g_qlo [(size_t)MM*DD*2/16];
__device__ uint4 g_khi [(size_t)MM*DD*2/16];
__device__ uint4 g_klo [(size_t)MM*DD*2/16];
__device__ uint4 g_vhi [(size_t)MM*DD*2/16];
__device__ uint4 g_vlo [(size_t)MM*DD*2/16];
__device__ uint4 g_mhi [(size_t)MM*DFF*2/16];
__device__ uint4 g_mlo [(size_t)MM*DFF*2/16];
__device__ uint4 g_wqkvth[(size_t)3*DD*DD*2/16];
__device__ uint4 g_wqkvtl[(size_t)3*DD*DD*2/16];
__device__ uint4 g_woth[(size_t)DD*DD*2/16];
__device__ uint4 g_wotl[(size_t)DD*DD*2/16];
__device__ uint4 g_w1th[(size_t)DD*DFF*2/16];
__device__ uint4 g_w1tl[(size_t)DD*DFF*2/16];
__device__ uint4 g_w2th[(size_t)DFF*DD*2/16];
__device__ uint4 g_w2tl[(size_t)DFF*DD*2/16];

// ---------------- PTX helpers (sm_80+ baseline) ------------------------------
__device__ __forceinline__ uint32_t smem_to_u32(const void* p) {
    uint32_t a;
    asm("{ .reg .u64 t; cvta.to.shared.u64 t, %1; cvt.u32.u64 %0, t; }" : "=r"(a) : "l"(p));
    return a;
}
__device__ __forceinline__ void cp16(uint32_t dst, const void* src) {
    asm volatile("cp.async.cg.shared.global [%0], [%1], 16;" :: "r"(dst), "l"(src) : "memory");
}
__device__ __forceinline__ void ldsm4(uint32_t* r, uint32_t a) {
    asm volatile("ldmatrix.sync.aligned.m8n8.x4.shared.b16 {%0,%1,%2,%3}, [%4];"
        : "=r"(r[0]), "=r"(r[1]), "=r"(r[2]), "=r"(r[3]) : "r"(a));
}
__device__ __forceinline__ void ldsm4t(uint32_t* r, uint32_t a) {
    asm volatile("ldmatrix.sync.aligned.m8n8.x4.trans.shared.b16 {%0,%1,%2,%3}, [%4];"
        : "=r"(r[0]), "=r"(r[1]), "=r"(r[2]), "=r"(r[3]) : "r"(a));
}
__device__ __forceinline__ void mma16816(float* d, const uint32_t* a, const uint32_t* b) {
    asm volatile("mma.sync.aligned.m16n8k16.row.col.f32.bf16.bf16.f32 "
        "{%0,%1,%2,%3}, {%4,%5,%6,%7}, {%8,%9}, {%0,%1,%2,%3};"
        : "+f"(d[0]), "+f"(d[1]), "+f"(d[2]), "+f"(d[3])
        : "r"(a[0]), "r"(a[1]), "r"(a[2]), "r"(a[3]), "r"(b[0]), "r"(b[1]));
}
__device__ __forceinline__ void packhl(float x, float y, uint32_t& hi, uint32_t& lo) {
    __nv_bfloat16 hx = __float2bfloat16_rn(x), hy = __float2bfloat16_rn(y);
    __nv_bfloat16 lx = __float2bfloat16_rn(x - __bfloat162float(hx));
    __nv_bfloat16 ly = __float2bfloat16_rn(y - __bfloat162float(hy));
    __nv_bfloat162 h2 = __halves2bfloat162(hx, hy), l2 = __halves2bfloat162(lx, ly);
    hi = *(uint32_t*)&h2; lo = *(uint32_t*)&l2;
}

// ---------------- LayerNorm with vectorized hi/lo split output ---------------
__global__ __launch_bounds__(256) void ln_split_kernel(
    const float* __restrict__ x, const float* __restrict__ g,
    const float* __restrict__ b,
    __nv_bfloat16* __restrict__ ohi, __nv_bfloat16* __restrict__ olo)
{
    int row = blockIdx.x;
    int t = threadIdx.x;
    const float* xr = x + (size_t)row * DD;
    float4 v = *(const float4*)(xr + 4*t);
    float s = v.x + v.y + v.z + v.w;

    __shared__ float warpsum[8];
    __shared__ float s_mean, s_inv;
    int lane = t & 31, wid = t >> 5;
#pragma unroll
    for (int o = 16; o > 0; o >>= 1) s += __shfl_xor_sync(~0u, s, o);
    if (lane == 0) warpsum[wid] = s;
    __syncthreads();
    if (t == 0) {
        float tot = 0.f;
#pragma unroll
        for (int i = 0; i < 8; i++) tot += warpsum[i];
        s_mean = tot * (1.f/DD);
    }
    __syncthreads();
    float mean = s_mean;
    float d0 = v.x-mean, d1 = v.y-mean, d2 = v.z-mean, d3 = v.w-mean;
    float ss = d0*d0 + d1*d1 + d2*d2 + d3*d3;
#pragma unroll
    for (int o = 16; o > 0; o >>= 1) ss += __shfl_xor_sync(~0u, ss, o);
    if (lane == 0) warpsum[wid] = ss;
    __syncthreads();
    if (t == 0) {
        float tot = 0.f;
#pragma unroll
        for (int i = 0; i < 8; i++) tot += warpsum[i];
        s_inv = rsqrtf(tot * (1.f/DD) + LNEPS);
    }
    __syncthreads();
    float inv = s_inv;

    float4 gv = *(const float4*)(g + 4*t);
    float4 bv = *(const float4*)(b + 4*t);
    float o0 = d0 * inv * gv.x + bv.x;
    float o1 = d1 * inv * gv.y + bv.y;
    float o2 = d2 * inv * gv.z + bv.z;
    float o3 = d3 * inv * gv.w + bv.w;
    uint32_t h01, l01, h23, l23;
    packhl(o0, o1, h01, l01);
    packhl(o2, o3, h23, l23);
    uint2 hv; hv.x = h01; hv.y = h23;
    uint2 lv; lv.x = l01; lv.y = l23;
    *(uint2*)(ohi + (size_t)row*DD + 4*t) = hv;
    *(uint2*)(olo + (size_t)row*DD + 4*t) = lv;
}

// ---------------- bias concat -------------------------------------------------
__global__ void concat3_kernel(const float* __restrict__ a, const float* __restrict__ b,
                               const float* __restrict__ c, float* __restrict__ o)
{
    int i = blockIdx.x * 256 + threadIdx.x;
    if (i < DD) o[i] = a[i];
    else if (i < 2*DD) o[i] = b[i - DD];
    else o[i] = c[i - 2*DD];
}

// ---------------- ALL weight transposes in ONE launch -------------------------
// W[K][N] -> T[N][K] hi/lo, 64(k) x 32(n) tiles, packed uint32 stores.
// Flat grid 6144: [0,2048) wq/wk/wv/wo (512 tiles each); [2048,4096) w1;
// [4096,6144) w2.
__global__ __launch_bounds__(256) void transpose_all_kernel(
    const float* __restrict__ wq, const float* __restrict__ wk,
    const float* __restrict__ wv, const float* __restrict__ wo,
    const float* __restrict__ w1, const float* __restrict__ w2,
    __nv_bfloat16* __restrict__ qkvh, __nv_bfloat16* __restrict__ qkvl,
    __nv_bfloat16* __restrict__ woh,  __nv_bfloat16* __restrict__ wol,
    __nv_bfloat16* __restrict__ w1h,  __nv_bfloat16* __restrict__ w1l,
    __nv_bfloat16* __restrict__ w2h,  __nv_bfloat16* __restrict__ w2l)
{
    int id = blockIdx.x;
    const float* W; __nv_bfloat16 *Th, *Tl;
    int K, N, n0, k0;
    if (id < 2048) {
        int m = id >> 9;
        int t = id & 511;
        n0 = (t & 31) * 32; k0 = (t >> 5) * 64;
        K = DD; N = DD;
        if (m == 0)      { W = wq; Th = qkvh;                        Tl = qkvl; }
        else if (m == 1) { W = wk; Th = qkvh + (size_t)DD*DD;        Tl = qkvl + (size_t)DD*DD; }
        else if (m == 2) { W = wv; Th = qkvh + (size_t)2*DD*DD;      Tl = qkvl + (size_t)2*DD*DD; }
        else             { W = wo; Th = woh;                         Tl = wol; }
    } else if (id < 4096) {
        int t = id - 2048;
        n0 = (t & 127) * 32; k0 = (t >> 7) * 64;
        K = DD; N = DFF;
        W = w1; Th = w1h; Tl = w1l;
    } else {
        int t = id - 4096;
        n0 = (t & 31) * 32; k0 = (t >> 5) * 64;
        K = DFF; N = DD;
        W = w2; Th = w2h; Tl = w2l;
    }

    __shared__ float tile[64][33];
    int tx = threadIdx.x, ty = threadIdx.y;  // 32 x 8
#pragma unroll
    for (int r = 0; r < 8; r++)
        tile[ty + 8*r][tx] = W[(size_t)(k0 + ty + 8*r) * N + n0 + tx];
    __syncthreads();
#pragma unroll
    for (int r = 0; r < 4; r++) {
        int nn = ty + 8*r;
        float v0 = tile[2*tx  ][nn];
        float v1 = tile[2*tx+1][nn];
        uint32_t hi, lo;
        packhl(v0, v1, hi, lo);
        size_t oi = (size_t)(n0 + nn) * K + k0 + 2*tx;
        *(uint32_t*)(Th + oi) = hi;
        *(uint32_t*)(Tl + oi) = lo;
    }
}

// ---------------- warp-MMA split-bf16 GEMM (128x128, 3-stage) ----------------
// C = A @ B^T : A [M,K] hi/lo, B [N,K] hi/lo. 8 warps of 64x32.
// Register double-buffered ks pipeline: LDSM(ks+1) issued before MMA(ks).
// MODE: 0 = fp32 out + residual; 2 = gelu + split hi/lo out; 3 = fused QKV route
#define SUBB   (128*144)
#define STAGEB (4*SUBB)              // 73728 B
#define GSMEM_BYTES (3*STAGEB)       // 221184 B

__device__ __forceinline__ void ld_chunk(uint32_t s0, int tid,
    const char* a0, const char* a1, const char* b0, const char* b1,
    size_t strb, int kc)
{
    const char* bases[4] = { a0, a1, b0, b1 };
#pragma unroll
    for (int mtx = 0; mtx < 4; mtx++) {
        const char* base = bases[mtx];
#pragma unroll
        for (int t = 0; t < 4; t++) {
            int seg = t*256 + tid;
            int r = seg >> 3, s = seg & 7;
            cp16(s0 + mtx*SUBB + r*144 + s*16,
                 base + (size_t)r * strb + (size_t)kc * 128 + s*16);
        }
    }
    asm volatile("cp.async.commit_group;" ::: "memory");
}

__device__ __forceinline__ void load_frags(
    uint32_t (&ah)[4][4], uint32_t (&al)[4][4],
    uint32_t (&bh)[2][4], uint32_t (&bl)[2][4],
    uint32_t a_base, uint32_t b_base, int ks)
{
#pragma unroll
    for (int mi = 0; mi < 4; mi++) {
        uint32_t ad = a_base + mi*16*144 + ks*32;
        ldsm4(ah[mi], ad);
        ldsm4(al[mi], ad + SUBB);
    }
#pragma unroll
    for (int bj = 0; bj < 2; bj++) {
        uint32_t bd = b_base + bj*16*144 + ks*32;
        ldsm4(bh[bj], bd);
        ldsm4(bl[bj], bd + SUBB);
    }
}

template<int MODE>
__global__ __launch_bounds__(256) void gemm_mma(
    const __nv_bfloat16* __restrict__ Ahi, const __nv_bfloat16* __restrict__ Alo,
    const __nv_bfloat16* __restrict__ Bhi, const __nv_bfloat16* __restrict__ Blo,
    const float* __restrict__ bias, const float* __restrict__ res,
    float* __restrict__ C,
    __nv_bfloat16* __restrict__ O0h, __nv_bfloat16* __restrict__ O0l,
    __nv_bfloat16* __restrict__ O1h, __nv_bfloat16* __restrict__ O1l,
    __nv_bfloat16* __restrict__ O2h, __nv_bfloat16* __restrict__ O2l,
    int N, int K)
{
    extern __shared__ char smem[];
    uint32_t sb = smem_to_u32(smem);
    int tid = threadIdx.x, lane = tid & 31, wid = tid >> 5;
    int m0 = blockIdx.y * 128, n0 = blockIdx.x * 128;
    int wr = wid >> 2, wc = wid & 3;

    size_t strb = (size_t)K * 2;
    const char* a0 = (const char*)(Ahi + (size_t)m0 * K);
    const char* a1 = (const char*)(Alo + (size_t)m0 * K);
    const char* b0 = (const char*)(Bhi + (size_t)n0 * K);
    const char* b1 = (const char*)(Blo + (size_t)n0 * K);

    float acc[4][4][4];
#pragma unroll
    for (int i = 0; i < 4; i++)
#pragma unroll
        for (int j = 0; j < 4; j++)
#pragma unroll
            for (int r = 0; r < 4; r++) acc[i][j][r] = 0.f;

    int NC = K >> 6;
    ld_chunk(sb, tid, a0, a1, b0, b1, strb, 0);
    if (NC > 1) ld_chunk(sb + STAGEB, tid, a0, a1, b0, b1, strb, 1);

    int cs = 0, ns = 2;
    for (int i = 0; i < NC; i++) {
        if (i + 1 < NC) { asm volatile("cp.async.wait_group 1;" ::: "memory"); }
        else            { asm volatile("cp.async.wait_group 0;" ::: "memory"); }
        __syncthreads();

        uint32_t st = sb + cs*STAGEB;
        uint32_t a_base = st + (wr*64 + (lane & 15))*144 + (lane >> 4)*16;
        uint32_t b_base = st + 2*SUBB +
            (wc*32 + (lane & 7) + ((lane >> 4) & 1)*8)*144 + ((lane >> 3) & 1)*16;

        uint32_t ah[2][4][4], al[2][4][4], bh[2][2][4], bl[2][2][4];
        load_frags(ah[0], al[0], bh[0], bl[0], a_base, b_base, 0);

#pragma unroll
        for (int ks = 0; ks < 4; ks++) {
            int cur = ks & 1;
            if (ks < 3)
                load_frags(ah[cur^1], al[cur^1], bh[cur^1], bl[cur^1],
                           a_base, b_base, ks + 1);
#pragma unroll
            for (int mi = 0; mi < 4; mi++) {
#pragma unroll
                for (int nj = 0; nj < 4; nj++) {
                    const uint32_t* bH = &bh[cur][nj >> 1][(nj & 1)*2];
                    const uint32_t* bL = &bl[cur][nj >> 1][(nj & 1)*2];
                    mma16816(acc[mi][nj], ah[cur][mi], bH);
                    mma16816(acc[mi][nj], ah[cur][mi], bL);
                    mma16816(acc[mi][nj], al[cur][mi], bH);
                }
            }
        }

        if (i + 2 < NC)
            ld_chunk(sb + ns*STAGEB, tid, a0, a1, b0, b1, strb, i + 2);
        cs = (cs + 1 == 3) ? 0 : cs + 1;
        ns = (ns + 1 == 3) ? 0 : ns + 1;
    }

    // ---- epilogue ----
    __nv_bfloat16 *oh = O0h, *ol = O0l;
    int lc0 = n0;
    float scale = 1.0f;
    if (MODE == 3) {
        int mat = n0 >> 10;
        lc0 = n0 & 1023;
        oh = (mat == 0) ? O0h : ((mat == 1) ? O1h : O2h);
        ol = (mat == 0) ? O0l : ((mat == 1) ? O1l : O2l);
        scale = (mat == 0) ? 0.125f : 1.0f;
    }

    float bx[4], by[4];
#pragma unroll
    for (int nj = 0; nj < 4; nj++) {
        int c = n0 + wc*32 + nj*8 + (lane & 3)*2;
        bx[nj] = bias[c]; by[nj] = bias[c+1];
    }
#pragma unroll
    for (int mi = 0; mi < 4; mi++) {
        int rbase = m0 + wr*64 + mi*16 + (lane >> 2);
#pragma unroll
        for (int half = 0; half < 2; half++) {
            int r = rbase + half*8;
#pragma unroll
            for (int nj = 0; nj < 4; nj++) {
                int cc = wc*32 + nj*8 + (lane & 3)*2;
                float v0 = acc[mi][nj][half*2+0] + bx[nj];
                float v1 = acc[mi][nj][half*2+1] + by[nj];
                if (MODE == 2) {
                    v0 = 0.5f * v0 * (1.f + erff(v0 * 0.70710678118654752f));
                    v1 = 0.5f * v1 * (1.f + erff(v1 * 0.70710678118654752f));
                }
                if (MODE == 0) {
                    int c = n0 + cc;
                    float2 rv = *(const float2*)(res + (size_t)r * N + c);
                    float2 o; o.x = v0 + rv.x; o.y = v1 + rv.y;
                    *(float2*)(C + (size_t)r * N + c) = o;
                } else if (MODE == 2) {
                    uint32_t hi, lo;
                    packhl(v0, v1, hi, lo);
                    int c = n0 + cc;
                    *(uint32_t*)(oh + (size_t)r * N + c) = hi;
                    *(uint32_t*)(ol + (size_t)r * N + c) = lo;
                } else { // MODE 3
                    v0 *= scale; v1 *= scale;
                    uint32_t hi, lo;
                    packhl(v0, v1, hi, lo);
                    int c = lc0 + cc;
                    *(uint32_t*)(oh + (size_t)r * DD + c) = hi;
                    *(uint32_t*)(ol + (size_t)r * DD + c) = lo;
                }
            }
        }
    }
}

// ---------------- fused flash attention (110.5KB, 2 CTA/SM) ------------------
#define FQH 0
#define FQL 18432
#define FKH 36864
#define FKL 55296
#define FVH 73728
#define FVL 92160
#define FSMEM 110592

__device__ __forceinline__ void fl_load_tile(uint32_t dst, int tid, const char* g)
{
#pragma unroll
    for (int t = 0; t < 4; t++) {
        int seg = t*256 + tid;
        int r = seg >> 3, s = seg & 7;
        cp16(dst + r*144 + s*16, g + (size_t)r * (DD*2) + s*16);
    }
}

__global__ __launch_bounds__(256) void flash_kernel(
    const __nv_bfloat16* __restrict__ qhi, const __nv_bfloat16* __restrict__ qlo,
    const __nv_bfloat16* __restrict__ khi, const __nv_bfloat16* __restrict__ klo,
    const __nv_bfloat16* __restrict__ vhi, const __nv_bfloat16* __restrict__ vlo,
    __nv_bfloat16* __restrict__ chi, __nv_bfloat16* __restrict__ clo)
{
    extern __shared__ char smem[];
    uint32_t sb = smem_to_u32(smem);
    int tid = threadIdx.x, lane = tid & 31, w = tid >> 5;
    int q0 = blockIdx.x * 128;
    int bh = blockIdx.y, b = bh >> 4, h = bh & 15;

    size_t qoff = ((size_t)(b*SS + q0) * DD + h*HDm) * 2;
    size_t koff = ((size_t)(b*SS) * DD + h*HDm) * 2;

    fl_load_tile(sb + FQH, tid, (const char*)qhi + qoff);
    fl_load_tile(sb + FQL, tid, (const char*)qlo + qoff);
    fl_load_tile(sb + FKH, tid, (const char*)khi + koff);
    fl_load_tile(sb + FKL, tid, (const char*)klo + koff);
    fl_load_tile(sb + FVH, tid, (const char*)vhi + koff);
    fl_load_tile(sb + FVL, tid, (const char*)vlo + koff);
    asm volatile("cp.async.commit_group;" ::: "memory");

    float oacc[8][4];
#pragma unroll
    for (int i = 0; i < 8; i++)
#pragma unroll
        for (int r = 0; r < 4; r++) oacc[i][r] = 0.f;
    float mrow[2] = { -1e30f, -1e30f };
    float lrow[2] = { 0.f, 0.f };

    uint32_t a_base = sb + FQH + (w*16 + (lane & 15))*144 + (lane >> 4)*16;

    for (int j = 0; j < SS/128; j++) {
        asm volatile("cp.async.wait_group 0;" ::: "memory");
        __syncthreads();

        float sacc[16][4];
#pragma unroll
        for (int i = 0; i < 16; i++)
#pragma unroll
            for (int r = 0; r < 4; r++) sacc[i][r] = 0.f;

#pragma unroll
        for (int ks = 0; ks < 4; ks++) {
            uint32_t ah[4], al[4];
            ldsm4(ah, a_base + ks*32);
            ldsm4(al, a_base + (FQL-FQH) + ks*32);
#pragma unroll
            for (int nt = 0; nt < 8; nt++) {
                uint32_t bh4[4], bl4[4];
                uint32_t bd = sb + FKH + (nt*16 + (lane & 7) + ((lane >> 4) & 1)*8)*144
                            + ((lane >> 3) & 1)*16 + ks*32;
                ldsm4(bh4, bd);
                ldsm4(bl4, bd + (FKL-FKH));
#pragma unroll
                for (int half = 0; half < 2; half++) {
                    mma16816(sacc[2*nt+half], ah, &bh4[half*2]);
                    mma16816(sacc[2*nt+half], ah, &bl4[half*2]);
                    mma16816(sacc[2*nt+half], al, &bh4[half*2]);
                }
            }
        }

#pragma unroll
        for (int half = 0; half < 2; half++) {
            float mx = -1e30f;
#pragma unroll
            for (int nt = 0; nt < 16; nt++) {
                mx = fmaxf(mx, sacc[nt][half*2+0]);
                mx = fmaxf(mx, sacc[nt][half*2+1]);
            }
            mx = fmaxf(mx, __shfl_xor_sync(~0u, mx, 1));
            mx = fmaxf(mx, __shfl_xor_sync(~0u, mx, 2));
            float mnew = fmaxf(mrow[half], mx);
            float alpha = __expf(mrow[half] - mnew);
            mrow[half] = mnew;
            float sum = 0.f;
#pragma unroll
            for (int nt = 0; nt < 16; nt++) {
                float p0 = __expf(sacc[nt][half*2+0] - mnew);
                float p1 = __expf(sacc[nt][half*2+1] - mnew);
                sacc[nt][half*2+0] = p0; sacc[nt][half*2+1] = p1;
                sum += p0 + p1;
            }
            lrow[half] = lrow[half] * alpha + sum;
#pragma unroll
            for (int on = 0; on < 8; on++) {
                oacc[on][half*2+0] *= alpha;
                oacc[on][half*2+1] *= alpha;
            }
        }

#pragma unroll
        for (int kt = 0; kt < 8; kt++) {
            uint32_t phi[4], plo[4];
            packhl(sacc[2*kt  ][0], sacc[2*kt  ][1], phi[0], plo[0]);
            packhl(sacc[2*kt  ][2], sacc[2*kt  ][3], phi[1], plo[1]);
            packhl(sacc[2*kt+1][0], sacc[2*kt+1][1], phi[2], plo[2]);
            packhl(sacc[2*kt+1][2], sacc[2*kt+1][3], phi[3], plo[3]);
#pragma unroll
            for (int np = 0; np < 4; np++) {
                uint32_t vh4[4], vl4[4];
                uint32_t vd = sb + FVH + (16*kt + (lane & 15))*144
                            + (np*16 + (lane >> 4)*8)*2;
                ldsm4t(vh4, vd);
                ldsm4t(vl4, vd + (FVL-FVH));
#pragma unroll
                for (int half = 0; half < 2; half++) {
                    mma16816(oacc[2*np+half], phi, &vh4[half*2]);
                    mma16816(oacc[2*np+half], phi, &vl4[half*2]);
                    mma16816(oacc[2*np+half], plo, &vh4[half*2]);
                }
            }
        }

        __syncthreads();
        if (j + 1 < SS/128) {
            size_t off = koff + (size_t)(j+1) * 128 * DD * 2;
            fl_load_tile(sb + FKH, tid, (const char*)khi + off);
            fl_load_tile(sb + FKL, tid, (const char*)klo + off);
            fl_load_tile(sb + FVH, tid, (const char*)vhi + off);
            fl_load_tile(sb + FVL, tid, (const char*)vlo + off);
            asm volatile("cp.async.commit_group;" ::: "memory");
        }
    }

#pragma unroll
    for (int half = 0; half < 2; half++) {
        float l = lrow[half];
        l += __shfl_xor_sync(~0u, l, 1);
        l += __shfl_xor_sync(~0u, l, 2);
        float inv = 1.f / l;
        int r = b*SS + q0 + w*16 + (lane >> 2) + half*8;
#pragma unroll
        for (int on = 0; on < 8; on++) {
            int c = h*HDm + on*8 + (lane & 3)*2;
            float v0 = oacc[on][half*2+0] * inv;
            float v1 = oacc[on][half*2+1] * inv;
            uint32_t hi, lo;
            packhl(v0, v1, hi, lo);
            *(uint32_t*)(chi + (size_t)r * DD + c) = hi;
            *(uint32_t*)(clo + (size_t)r * DD + c) = lo;
        }
    }
}

// ---------------- launch ------------------------------------------------------
extern "C" void kernel_launch(void* const* d_in, const int* in_sizes, int n_in,
                              void* d_out, int out_size)
{
    const float* x    = (const float*)d_in[0];
    const float* ln1g = (const float*)d_in[1];
    const float* ln1b = (const float*)d_in[2];
    const float* wq   = (const float*)d_in[3];
    const float* bq   = (const float*)d_in[4];
    const float* wk   = (const float*)d_in[5];
    const float* bk   = (const float*)d_in[6];
    const float* wv   = (const float*)d_in[7];
    const float* bv   = (const float*)d_in[8];
    const float* wo   = (const float*)d_in[9];
    const float* bo   = (const float*)d_in[10];
    const float* ln2g = (const float*)d_in[11];
    const float* ln2b = (const float*)d_in[12];
    const float* w1   = (const float*)d_in[13];
    const float* b1   = (const float*)d_in[14];
    const float* w2   = (const float*)d_in[15];
    const float* b2   = (const float*)d_in[16];
    float* out = (float*)d_out;

    float *x2, *bqkv;
    cudaGetSymbolAddress((void**)&x2, g_x2);
    cudaGetSymbolAddress((void**)&bqkv, g_bqkv);

    __nv_bfloat16 *ahi, *alo, *qhi, *qlo, *khi, *klo, *vhi, *vlo, *mhi, *mlo;
    __nv_bfloat16 *wqkvth, *wqkvtl, *woth, *wotl, *w1th, *w1tl, *w2th, *w2tl;
    cudaGetSymbolAddress((void**)&ahi,  g_ahi);
    cudaGetSymbolAddress((void**)&alo,  g_alo);
    cudaGetSymbolAddress((void**)&qhi,  g_qhi);
    cudaGetSymbolAddress((void**)&qlo,  g_qlo);
    cudaGetSymbolAddress((void**)&khi,  g_khi);
    cudaGetSymbolAddress((void**)&klo,  g_klo);
    cudaGetSymbolAddress((void**)&vhi,  g_vhi);
    cudaGetSymbolAddress((void**)&vlo,  g_vlo);
    cudaGetSymbolAddress((void**)&mhi,  g_mhi);
    cudaGetSymbolAddress((void**)&mlo,  g_mlo);
    cudaGetSymbolAddress((void**)&wqkvth, g_wqkvth);
    cudaGetSymbolAddress((void**)&wqkvtl, g_wqkvtl);
    cudaGetSymbolAddress((void**)&woth, g_woth);
    cudaGetSymbolAddress((void**)&wotl, g_wotl);
    cudaGetSymbolAddress((void**)&w1th, g_w1th);
    cudaGetSymbolAddress((void**)&w1tl, g_w1tl);
    cudaGetSymbolAddress((void**)&w2th, g_w2th);
    cudaGetSymbolAddress((void**)&w2tl, g_w2tl);

    cudaFuncSetAttribute(gemm_mma<0>, cudaFuncAttributeMaxDynamicSharedMemorySize, GSMEM_BYTES);
    cudaFuncSetAttribute(gemm_mma<2>, cudaFuncAttributeMaxDynamicSharedMemorySize, GSMEM_BYTES);
    cudaFuncSetAttribute(gemm_mma<3>, cudaFuncAttributeMaxDynamicSharedMemorySize, GSMEM_BYTES);
    cudaFuncSetAttribute(flash_kernel, cudaFuncAttributeMaxDynamicSharedMemorySize, FSMEM);

    dim3 tb(32, 8);

    // 0: h1 = LN(x) -> hi/lo
    ln_split_kernel<<<MM, 256>>>(x, ln1g, ln1b, ahi, alo);
    // 1: bias concat
    concat3_kernel<<<12, 256>>>(bq, bk, bv, bqkv);
    // 2: ALL weight transposes in one launch
    transpose_all_kernel<<<6144, tb>>>(wq, wk, wv, wo, w1, w2,
        wqkvth, wqkvtl, woth, wotl, w1th, w1tl, w2th, w2tl);

    // 3: fused QKV projection -> q/k/v hi/lo (Q pre-scaled by 1/8)
    dim3 gqkv(3*DD/128, MM/128);
    gemm_mma<3><<<gqkv, 256, GSMEM_BYTES>>>(ahi, alo, wqkvth, wqkvtl, bqkv, nullptr,
        nullptr, qhi, qlo, khi, klo, vhi, vlo, 3*DD, DD);

    // 4: fused flash attention -> ctx hi/lo (reuse ahi/alo)
    flash_kernel<<<dim3(SS/128, BB*HH), 256, FSMEM>>>(
        qhi, qlo, khi, klo, vhi, vlo, ahi, alo);

    // 5: x2 = x + ctx @ wo + bo  (fp32 out)
    dim3 g1(DD/128, MM/128);
    gemm_mma<0><<<g1, 256, GSMEM_BYTES>>>(ahi, alo, woth, wotl, bo, x,
        x2, nullptr, nullptr, nullptr, nullptr, nullptr, nullptr, DD, DD);

    // 6: h2 = LN(x2) -> hi/lo (reuse qhi/qlo)
    ln_split_kernel<<<MM, 256>>>(x2, ln2g, ln2b, qhi, qlo);

    // 7: mlp = gelu(h2 @ w1 + b1) -> hi/lo
    dim3 g2(DFF/128, MM/128);
    gemm_mma<2><<<g2, 256, GSMEM_BYTES>>>(qhi, qlo, w1th, w1tl, b1, nullptr,
        nullptr, mhi, mlo, nullptr, nullptr, nullptr, nullptr, DFF, DD);

    // 8: out = x2 + mlp @ w2 + b2
    gemm_mma<0><<<g1, 256, GSMEM_BYTES>>>(mhi, mlo, w2th, w2tl, b2, x2,
        out, nullptr, nullptr, nullptr, nullptr, nullptr, nullptr, DD, DFF);
}

// round 16
// speedup vs baseline: 1.1916x; 1.1197x over previous
#include <cuda_runtime.h>
#include <cuda_bf16.h>
#include <math.h>
#include <stdint.h>

#define BB  4
#define SS  1024
#define DD  1024
#define HH  16
#define HDm 64
#define MM  (BB*SS)      // 4096
#define DFF (4*DD)       // 4096
#define LNEPS 1e-5f

// ---------------- scratch ----------------------------------------------------
__device__ float g_x2 [(size_t)MM*DD];
__device__ float g_bqkv[3*DD];

// bf16 hi/lo buffers (uint4 => 16B aligned)
__device__ uint4 g_ahi [(size_t)MM*DD*2/16];   // h1 -> later ctx
__device__ uint4 g_alo [(size_t)MM*DD*2/16];
__device__ uint4 g_qhi [(size_t)MM*DD*2/16];   // q -> later h2
__device__ uint4 g_qlo [(size_t)MM*DD*2/16];
__device__ uint4 g_khi [(size_t)MM*DD*2/16];
__device__ uint4 g_klo [(size_t)MM*DD*2/16];
__device__ uint4 g_vhi [(size_t)MM*DD*2/16];
__device__ uint4 g_vlo [(size_t)MM*DD*2/16];
__device__ uint4 g_mhi [(size_t)MM*DFF*2/16];
__device__ uint4 g_mlo [(size_t)MM*DFF*2/16];
__device__ uint4 g_wqkvth[(size_t)3*DD*DD*2/16];
__device__ uint4 g_wqkvtl[(size_t)3*DD*DD*2/16];
__device__ uint4 g_woth[(size_t)DD*DD*2/16];
__device__ uint4 g_wotl[(size_t)DD*DD*2/16];
__device__ uint4 g_w1th[(size_t)DD*DFF*2/16];
__device__ uint4 g_w1tl[(size_t)DD*DFF*2/16];
__device__ uint4 g_w2th[(size_t)DFF*DD*2/16];
__device__ uint4 g_w2tl[(size_t)DFF*DD*2/16];

// ---------------- PTX helpers (sm_80+ baseline) ------------------------------
__device__ __forceinline__ uint32_t smem_to_u32(const void* p) {
    uint32_t a;
    asm("{ .reg .u64 t; cvta.to.shared.u64 t, %1; cvt.u32.u64 %0, t; }" : "=r"(a) : "l"(p));
    return a;
}
__device__ __forceinline__ void cp16(uint32_t dst, const void* src) {
    asm volatile("cp.async.cg.shared.global [%0], [%1], 16;" :: "r"(dst), "l"(src) : "memory");
}
__device__ __forceinline__ void ldsm4(uint32_t* r, uint32_t a) {
    asm volatile("ldmatrix.sync.aligned.m8n8.x4.shared.b16 {%0,%1,%2,%3}, [%4];"
        : "=r"(r[0]), "=r"(r[1]), "=r"(r[2]), "=r"(r[3]) : "r"(a));
}
__device__ __forceinline__ void ldsm4t(uint32_t* r, uint32_t a) {
    asm volatile("ldmatrix.sync.aligned.m8n8.x4.trans.shared.b16 {%0,%1,%2,%3}, [%4];"
        : "=r"(r[0]), "=r"(r[1]), "=r"(r[2]), "=r"(r[3]) : "r"(a));
}
__device__ __forceinline__ void mma16816(float* d, const uint32_t* a, const uint32_t* b) {
    asm volatile("mma.sync.aligned.m16n8k16.row.col.f32.bf16.bf16.f32 "
        "{%0,%1,%2,%3}, {%4,%5,%6,%7}, {%8,%9}, {%0,%1,%2,%3};"
        : "+f"(d[0]), "+f"(d[1]), "+f"(d[2]), "+f"(d[3])
        : "r"(a[0]), "r"(a[1]), "r"(a[2]), "r"(a[3]), "r"(b[0]), "r"(b[1]));
}
__device__ __forceinline__ void packhl(float x, float y, uint32_t& hi, uint32_t& lo) {
    __nv_bfloat16 hx = __float2bfloat16_rn(x), hy = __float2bfloat16_rn(y);
    __nv_bfloat16 lx = __float2bfloat16_rn(x - __bfloat162float(hx));
    __nv_bfloat16 ly = __float2bfloat16_rn(y - __bfloat162float(hy));
    __nv_bfloat162 h2 = __halves2bfloat162(hx, hy), l2 = __halves2bfloat162(lx, ly);
    hi = *(uint32_t*)&h2; lo = *(uint32_t*)&l2;
}

// ---------------- LayerNorm with vectorized hi/lo split output ---------------
__global__ __launch_bounds__(256) void ln_split_kernel(
    const float* __restrict__ x, const float* __restrict__ g,
    const float* __restrict__ b,
    __nv_bfloat16* __restrict__ ohi, __nv_bfloat16* __restrict__ olo)
{
    int row = blockIdx.x;
    int t = threadIdx.x;
    const float* xr = x + (size_t)row * DD;
    float4 v = *(const float4*)(xr + 4*t);
    float s = v.x + v.y + v.z + v.w;

    __shared__ float warpsum[8];
    __shared__ float s_mean, s_inv;
    int lane = t & 31, wid = t >> 5;
#pragma unroll
    for (int o = 16; o > 0; o >>= 1) s += __shfl_xor_sync(~0u, s, o);
    if (lane == 0) warpsum[wid] = s;
    __syncthreads();
    if (t == 0) {
        float tot = 0.f;
#pragma unroll
        for (int i = 0; i < 8; i++) tot += warpsum[i];
        s_mean = tot * (1.f/DD);
    }
    __syncthreads();
    float mean = s_mean;
    float d0 = v.x-mean, d1 = v.y-mean, d2 = v.z-mean, d3 = v.w-mean;
    float ss = d0*d0 + d1*d1 + d2*d2 + d3*d3;
#pragma unroll
    for (int o = 16; o > 0; o >>= 1) ss += __shfl_xor_sync(~0u, ss, o);
    if (lane == 0) warpsum[wid] = ss;
    __syncthreads();
    if (t == 0) {
        float tot = 0.f;
#pragma unroll
        for (int i = 0; i < 8; i++) tot += warpsum[i];
        s_inv = rsqrtf(tot * (1.f/DD) + LNEPS);
    }
    __syncthreads();
    float inv = s_inv;

    float4 gv = *(const float4*)(g + 4*t);
    float4 bv = *(const float4*)(b + 4*t);
    float o0 = d0 * inv * gv.x + bv.x;
    float o1 = d1 * inv * gv.y + bv.y;
    float o2 = d2 * inv * gv.z + bv.z;
    float o3 = d3 * inv * gv.w + bv.w;
    uint32_t h01, l01, h23, l23;
    packhl(o0, o1, h01, l01);
    packhl(o2, o3, h23, l23);
    uint2 hv; hv.x = h01; hv.y = h23;
    uint2 lv; lv.x = l01; lv.y = l23;
    *(uint2*)(ohi + (size_t)row*DD + 4*t) = hv;
    *(uint2*)(olo + (size_t)row*DD + 4*t) = lv;
}

// ---------------- bias concat -------------------------------------------------
__global__ void concat3_kernel(const float* __restrict__ a, const float* __restrict__ b,
                               const float* __restrict__ c, float* __restrict__ o)
{
    int i = blockIdx.x * 256 + threadIdx.x;
    if (i < DD) o[i] = a[i];
    else if (i < 2*DD) o[i] = b[i - DD];
    else o[i] = c[i - 2*DD];
}

// ---------------- ALL weight transposes in ONE launch -------------------------
__global__ __launch_bounds__(256) void transpose_all_kernel(
    const float* __restrict__ wq, const float* __restrict__ wk,
    const float* __restrict__ wv, const float* __restrict__ wo,
    const float* __restrict__ w1, const float* __restrict__ w2,
    __nv_bfloat16* __restrict__ qkvh, __nv_bfloat16* __restrict__ qkvl,
    __nv_bfloat16* __restrict__ woh,  __nv_bfloat16* __restrict__ wol,
    __nv_bfloat16* __restrict__ w1h,  __nv_bfloat16* __restrict__ w1l,
    __nv_bfloat16* __restrict__ w2h,  __nv_bfloat16* __restrict__ w2l)
{
    int id = blockIdx.x;
    const float* W; __nv_bfloat16 *Th, *Tl;
    int K, N, n0, k0;
    if (id < 2048) {
        int m = id >> 9;
        int t = id & 511;
        n0 = (t & 31) * 32; k0 = (t >> 5) * 64;
        K = DD; N = DD;
        if (m == 0)      { W = wq; Th = qkvh;                        Tl = qkvl; }
        else if (m == 1) { W = wk; Th = qkvh + (size_t)DD*DD;        Tl = qkvl + (size_t)DD*DD; }
        else if (m == 2) { W = wv; Th = qkvh + (size_t)2*DD*DD;      Tl = qkvl + (size_t)2*DD*DD; }
        else             { W = wo; Th = woh;                         Tl = wol; }
    } else if (id < 4096) {
        int t = id - 2048;
        n0 = (t & 127) * 32; k0 = (t >> 7) * 64;
        K = DD; N = DFF;
        W = w1; Th = w1h; Tl = w1l;
    } else {
        int t = id - 4096;
        n0 = (t & 31) * 32; k0 = (t >> 5) * 64;
        K = DFF; N = DD;
        W = w2; Th = w2h; Tl = w2l;
    }

    __shared__ float tile[64][33];
    int tx = threadIdx.x, ty = threadIdx.y;  // 32 x 8
#pragma unroll
    for (int r = 0; r < 8; r++)
        tile[ty + 8*r][tx] = W[(size_t)(k0 + ty + 8*r) * N + n0 + tx];
    __syncthreads();
#pragma unroll
    for (int r = 0; r < 4; r++) {
        int nn = ty + 8*r;
        float v0 = tile[2*tx  ][nn];
        float v1 = tile[2*tx+1][nn];
        uint32_t hi, lo;
        packhl(v0, v1, hi, lo);
        size_t oi = (size_t)(n0 + nn) * K + k0 + 2*tx;
        *(uint32_t*)(Th + oi) = hi;
        *(uint32_t*)(Tl + oi) = lo;
    }
}

// ---------------- warp-MMA split-bf16 GEMM (128x128, BK=32, 3-stage, 2 CTA/SM)
// C = A @ B^T : A [M,K] hi/lo, B [N,K] hi/lo. 8 warps of 64x32.
// 64B rows with XOR chunk swizzle (conflict-free ldmatrix, no padding):
//   addr(r, s) = r*64 + (s ^ ((r>>1)&3))*16
// Stage = 4 sub-tiles x 8KB = 32KB; 3 stages = 96KB -> 2 CTAs/SM.
// MODE: 0 = fp32 out + residual; 2 = gelu + split hi/lo out; 3 = fused QKV route
#define SUBB   (128*64)              // 8192 B
#define STAGEB (4*SUBB)              // 32768 B
#define GSMEM_BYTES (3*STAGEB)       // 98304 B

__device__ __forceinline__ uint32_t swz(uint32_t r, uint32_t s) {
    return r*64 + ((s ^ ((r >> 1) & 3)) * 16);
}

__device__ __forceinline__ void ld_chunk(uint32_t s0, int tid,
    const char* a0, const char* a1, const char* b0, const char* b1,
    size_t strb, int kc)
{
    const char* bases[4] = { a0, a1, b0, b1 };
#pragma unroll
    for (int mtx = 0; mtx < 4; mtx++) {
        const char* base = bases[mtx];
#pragma unroll
        for (int t = 0; t < 2; t++) {
            int seg = t*256 + tid;
            int r = seg >> 2, s = seg & 3;
            cp16(s0 + mtx*SUBB + swz(r, s),
                 base + (size_t)r * strb + (size_t)kc * 64 + s*16);
        }
    }
    asm volatile("cp.async.commit_group;" ::: "memory");
}

template<int MODE>
__global__ __launch_bounds__(256, 2) void gemm_mma(
    const __nv_bfloat16* __restrict__ Ahi, const __nv_bfloat16* __restrict__ Alo,
    const __nv_bfloat16* __restrict__ Bhi, const __nv_bfloat16* __restrict__ Blo,
    const float* __restrict__ bias, const float* __restrict__ res,
    float* __restrict__ C,
    __nv_bfloat16* __restrict__ O0h, __nv_bfloat16* __restrict__ O0l,
    __nv_bfloat16* __restrict__ O1h, __nv_bfloat16* __restrict__ O1l,
    __nv_bfloat16* __restrict__ O2h, __nv_bfloat16* __restrict__ O2l,
    int N, int K)
{
    extern __shared__ char smem[];
    uint32_t sb = smem_to_u32(smem);
    int tid = threadIdx.x, lane = tid & 31, wid = tid >> 5;
    int m0 = blockIdx.y * 128, n0 = blockIdx.x * 128;
    int wr = wid >> 2, wc = wid & 3;

    size_t strb = (size_t)K * 2;
    const char* a0 = (const char*)(Ahi + (size_t)m0 * K);
    const char* a1 = (const char*)(Alo + (size_t)m0 * K);
    const char* b0 = (const char*)(Bhi + (size_t)n0 * K);
    const char* b1 = (const char*)(Blo + (size_t)n0 * K);

    float acc[4][4][4];
#pragma unroll
    for (int i = 0; i < 4; i++)
#pragma unroll
        for (int j = 0; j < 4; j++)
#pragma unroll
            for (int r = 0; r < 4; r++) acc[i][j][r] = 0.f;

    int NC = K >> 5;                 // 32-element K chunks
    ld_chunk(sb, tid, a0, a1, b0, b1, strb, 0);
    if (NC > 1) ld_chunk(sb + STAGEB, tid, a0, a1, b0, b1, strb, 1);

    int cs = 0, ns = 2;
    for (int i = 0; i < NC; i++) {
        if (i + 1 < NC) { asm volatile("cp.async.wait_group 1;" ::: "memory"); }
        else            { asm volatile("cp.async.wait_group 0;" ::: "memory"); }
        __syncthreads();

        uint32_t st = sb + cs*STAGEB;

#pragma unroll
        for (int ks = 0; ks < 2; ks++) {
            uint32_t ah[4][4], al[4][4], bh[2][4], bl[2][4];
#pragma unroll
            for (int mi = 0; mi < 4; mi++) {
                uint32_t r = wr*64 + (lane & 15) + mi*16;
                uint32_t s = (lane >> 4) + ks*2;
                uint32_t ad = st + swz(r, s);
                ldsm4(ah[mi], ad);
                ldsm4(al[mi], ad + SUBB);
            }
#pragma unroll
            for (int bj = 0; bj < 2; bj++) {
                uint32_t r = wc*32 + (lane & 7) + ((lane >> 4) & 1)*8 + bj*16;
                uint32_t s = ((lane >> 3) & 1) + ks*2;
                uint32_t bd = st + 2*SUBB + swz(r, s);
                ldsm4(bh[bj], bd);
                ldsm4(bl[bj], bd + SUBB);
            }
#pragma unroll
            for (int mi = 0; mi < 4; mi++) {
#pragma unroll
                for (int nj = 0; nj < 4; nj++) {
                    const uint32_t* bH = &bh[nj >> 1][(nj & 1)*2];
                    const uint32_t* bL = &bl[nj >> 1][(nj & 1)*2];
                    mma16816(acc[mi][nj], ah[mi], bH);
                    mma16816(acc[mi][nj], ah[mi], bL);
                    mma16816(acc[mi][nj], al[mi], bH);
                }
            }
        }

        if (i + 2 < NC)
            ld_chunk(sb + ns*STAGEB, tid, a0, a1, b0, b1, strb, i + 2);
        cs = (cs + 1 == 3) ? 0 : cs + 1;
        ns = (ns + 1 == 3) ? 0 : ns + 1;
    }

    // ---- epilogue ----
    __nv_bfloat16 *oh = O0h, *ol = O0l;
    int lc0 = n0;
    float scale = 1.0f;
    if (MODE == 3) {
        int mat = n0 >> 10;
        lc0 = n0 & 1023;
        oh = (mat == 0) ? O0h : ((mat == 1) ? O1h : O2h);
        ol = (mat == 0) ? O0l : ((mat == 1) ? O1l : O2l);
        scale = (mat == 0) ? 0.125f : 1.0f;
    }

    float bx[4], by[4];
#pragma unroll
    for (int nj = 0; nj < 4; nj++) {
        int c = n0 + wc*32 + nj*8 + (lane & 3)*2;
        bx[nj] = bias[c]; by[nj] = bias[c+1];
    }
#pragma unroll
    for (int mi = 0; mi < 4; mi++) {
        int rbase = m0 + wr*64 + mi*16 + (lane >> 2);
#pragma unroll
        for (int half = 0; half < 2; half++) {
            int r = rbase + half*8;
#pragma unroll
            for (int nj = 0; nj < 4; nj++) {
                int cc = wc*32 + nj*8 + (lane & 3)*2;
                float v0 = acc[mi][nj][half*2+0] + bx[nj];
                float v1 = acc[mi][nj][half*2+1] + by[nj];
                if (MODE == 2) {
                    v0 = 0.5f * v0 * (1.f + erff(v0 * 0.70710678118654752f));
                    v1 = 0.5f * v1 * (1.f + erff(v1 * 0.70710678118654752f));
                }
                if (MODE == 0) {
                    int c = n0 + cc;
                    float2 rv = *(const float2*)(res + (size_t)r * N + c);
                    float2 o; o.x = v0 + rv.x; o.y = v1 + rv.y;
                    *(float2*)(C + (size_t)r * N + c) = o;
                } else if (MODE == 2) {
                    uint32_t hi, lo;
                    packhl(v0, v1, hi, lo);
                    int c = n0 + cc;
                    *(uint32_t*)(oh + (size_t)r * N + c) = hi;
                    *(uint32_t*)(ol + (size_t)r * N + c) = lo;
                } else { // MODE 3
                    v0 *= scale; v1 *= scale;
                    uint32_t hi, lo;
                    packhl(v0, v1, hi, lo);
                    int c = lc0 + cc;
                    *(uint32_t*)(oh + (size_t)r * DD + c) = hi;
                    *(uint32_t*)(ol + (size_t)r * DD + c) = lo;
                }
            }
        }
    }
}

// ---------------- fused flash attention (110.5KB, 2 CTA/SM) ------------------
#define FQH 0
#define FQL 18432
#define FKH 36864
#define FKL 55296
#define FVH 73728
#define FVL 92160
#define FSMEM 110592

__device__ __forceinline__ void fl_load_tile(uint32_t dst, int tid, const char* g)
{
#pragma unroll
    for (int t = 0; t < 4; t++) {
        int seg = t*256 + tid;
        int r = seg >> 3, s = seg & 7;
        cp16(dst + r*144 + s*16, g + (size_t)r * (DD*2) + s*16);
    }
}

__global__ __launch_bounds__(256) void flash_kernel(
    const __nv_bfloat16* __restrict__ qhi, const __nv_bfloat16* __restrict__ qlo,
    const __nv_bfloat16* __restrict__ khi, const __nv_bfloat16* __restrict__ klo,
    const __nv_bfloat16* __restrict__ vhi, const __nv_bfloat16* __restrict__ vlo,
    __nv_bfloat16* __restrict__ chi, __nv_bfloat16* __restrict__ clo)
{
    extern __shared__ char smem[];
    uint32_t sb = smem_to_u32(smem);
    int tid = threadIdx.x, lane = tid & 31, w = tid >> 5;
    int q0 = blockIdx.x * 128;
    int bh = blockIdx.y, b = bh >> 4, h = bh & 15;

    size_t qoff = ((size_t)(b*SS + q0) * DD + h*HDm) * 2;
    size_t koff = ((size_t)(b*SS) * DD + h*HDm) * 2;

    fl_load_tile(sb + FQH, tid, (const char*)qhi + qoff);
    fl_load_tile(sb + FQL, tid, (const char*)qlo + qoff);
    fl_load_tile(sb + FKH, tid, (const char*)khi + koff);
    fl_load_tile(sb + FKL, tid, (const char*)klo + koff);
    fl_load_tile(sb + FVH, tid, (const char*)vhi + koff);
    fl_load_tile(sb + FVL, tid, (const char*)vlo + koff);
    asm volatile("cp.async.commit_group;" ::: "memory");

    float oacc[8][4];
#pragma unroll
    for (int i = 0; i < 8; i++)
#pragma unroll
        for (int r = 0; r < 4; r++) oacc[i][r] = 0.f;
    float mrow[2] = { -1e30f, -1e30f };
    float lrow[2] = { 0.f, 0.f };

    uint32_t a_base = sb + FQH + (w*16 + (lane & 15))*144 + (lane >> 4)*16;

    for (int j = 0; j < SS/128; j++) {
        asm volatile("cp.async.wait_group 0;" ::: "memory");
        __syncthreads();

        float sacc[16][4];
#pragma unroll
        for (int i = 0; i < 16; i++)
#pragma unroll
            for (int r = 0; r < 4; r++) sacc[i][r] = 0.f;

#pragma unroll
        for (int ks = 0; ks < 4; ks++) {
            uint32_t ah[4], al[4];
            ldsm4(ah, a_base + ks*32);
            ldsm4(al, a_base + (FQL-FQH) + ks*32);
#pragma unroll
            for (int nt = 0; nt < 8; nt++) {
                uint32_t bh4[4], bl4[4];
                uint32_t bd = sb + FKH + (nt*16 + (lane & 7) + ((lane >> 4) & 1)*8)*144
                            + ((lane >> 3) & 1)*16 + ks*32;
                ldsm4(bh4, bd);
                ldsm4(bl4, bd + (FKL-FKH));
#pragma unroll
                for (int half = 0; half < 2; half++) {
                    mma16816(sacc[2*nt+half], ah, &bh4[half*2]);
                    mma16816(sacc[2*nt+half], ah, &bl4[half*2]);
                    mma16816(sacc[2*nt+half], al, &bh4[half*2]);
                }
            }
        }

#pragma unroll
        for (int half = 0; half < 2; half++) {
            float mx = -1e30f;
#pragma unroll
            for (int nt = 0; nt < 16; nt++) {
                mx = fmaxf(mx, sacc[nt][half*2+0]);
                mx = fmaxf(mx, sacc[nt][half*2+1]);
            }
            mx = fmaxf(mx, __shfl_xor_sync(~0u, mx, 1));
            mx = fmaxf(mx, __shfl_xor_sync(~0u, mx, 2));
            float mnew = fmaxf(mrow[half], mx);
            float alpha = __expf(mrow[half] - mnew);
            mrow[half] = mnew;
            float sum = 0.f;
#pragma unroll
            for (int nt = 0; nt < 16; nt++) {
                float p0 = __expf(sacc[nt][half*2+0] - mnew);
                float p1 = __expf(sacc[nt][half*2+1] - mnew);
                sacc[nt][half*2+0] = p0; sacc[nt][half*2+1] = p1;
                sum += p0 + p1;
            }
            lrow[half] = lrow[half] * alpha + sum;
#pragma unroll
            for (int on = 0; on < 8; on++) {
                oacc[on][half*2+0] *= alpha;
                oacc[on][half*2+1] *= alpha;
            }
        }

#pragma unroll
        for (int kt = 0; kt < 8; kt++) {
            uint32_t phi[4], plo[4];
            packhl(sacc[2*kt  ][0], sacc[2*kt  ][1], phi[0], plo[0]);
            packhl(sacc[2*kt  ][2], sacc[2*kt  ][3], phi[1], plo[1]);
            packhl(sacc[2*kt+1][0], sacc[2*kt+1][1], phi[2], plo[2]);
            packhl(sacc[2*kt+1][2], sacc[2*kt+1][3], phi[3], plo[3]);
#pragma unroll
            for (int np = 0; np < 4; np++) {
                uint32_t vh4[4], vl4[4];
                uint32_t vd = sb + FVH + (16*kt + (lane & 15))*144
                            + (np*16 + (lane >> 4)*8)*2;
                ldsm4t(vh4, vd);
                ldsm4t(vl4, vd + (FVL-FVH));
#pragma unroll
                for (int half = 0; half < 2; half++) {
                    mma16816(oacc[2*np+half], phi, &vh4[half*2]);
                    mma16816(oacc[2*np+half], phi, &vl4[half*2]);
                    mma16816(oacc[2*np+half], plo, &vh4[half*2]);
                }
            }
        }

        __syncthreads();
        if (j + 1 < SS/128) {
            size_t off = koff + (size_t)(j+1) * 128 * DD * 2;
            fl_load_tile(sb + FKH, tid, (const char*)khi + off);
            fl_load_tile(sb + FKL, tid, (const char*)klo + off);
            fl_load_tile(sb + FVH, tid, (const char*)vhi + off);
            fl_load_tile(sb + FVL, tid, (const char*)vlo + off);
            asm volatile("cp.async.commit_group;" ::: "memory");
        }
    }

#pragma unroll
    for (int half = 0; half < 2; half++) {
        float l = lrow[half];
        l += __shfl_xor_sync(~0u, l, 1);
        l += __shfl_xor_sync(~0u, l, 2);
        float inv = 1.f / l;
        int r = b*SS + q0 + w*16 + (lane >> 2) + half*8;
#pragma unroll
        for (int on = 0; on < 8; on++) {
            int c = h*HDm + on*8 + (lane & 3)*2;
            float v0 = oacc[on][half*2+0] * inv;
            float v1 = oacc[on][half*2+1] * inv;
            uint32_t hi, lo;
            packhl(v0, v1, hi, lo);
            *(uint32_t*)(chi + (size_t)r * DD + c) = hi;
            *(uint32_t*)(clo + (size_t)r * DD + c) = lo;
        }
    }
}

// ---------------- launch ------------------------------------------------------
extern "C" void kernel_launch(void* const* d_in, const int* in_sizes, int n_in,
                              void* d_out, int out_size)
{
    const float* x    = (const float*)d_in[0];
    const float* ln1g = (const float*)d_in[1];
    const float* ln1b = (const float*)d_in[2];
    const float* wq   = (const float*)d_in[3];
    const float* bq   = (const float*)d_in[4];
    const float* wk   = (const float*)d_in[5];
    const float* bk   = (const float*)d_in[6];
    const float* wv   = (const float*)d_in[7];
    const float* bv   = (const float*)d_in[8];
    const float* wo   = (const float*)d_in[9];
    const float* bo   = (const float*)d_in[10];
    const float* ln2g = (const float*)d_in[11];
    const float* ln2b = (const float*)d_in[12];
    const float* w1   = (const float*)d_in[13];
    const float* b1   = (const float*)d_in[14];
    const float* w2   = (const float*)d_in[15];
    const float* b2   = (const float*)d_in[16];
    float* out = (float*)d_out;

    float *x2, *bqkv;
    cudaGetSymbolAddress((void**)&x2, g_x2);
    cudaGetSymbolAddress((void**)&bqkv, g_bqkv);

    __nv_bfloat16 *ahi, *alo, *qhi, *qlo, *khi, *klo, *vhi, *vlo, *mhi, *mlo;
    __nv_bfloat16 *wqkvth, *wqkvtl, *woth, *wotl, *w1th, *w1tl, *w2th, *w2tl;
    cudaGetSymbolAddress((void**)&ahi,  g_ahi);
    cudaGetSymbolAddress((void**)&alo,  g_alo);
    cudaGetSymbolAddress((void**)&qhi,  g_qhi);
    cudaGetSymbolAddress((void**)&qlo,  g_qlo);
    cudaGetSymbolAddress((void**)&khi,  g_khi);
    cudaGetSymbolAddress((void**)&klo,  g_klo);
    cudaGetSymbolAddress((void**)&vhi,  g_vhi);
    cudaGetSymbolAddress((void**)&vlo,  g_vlo);
    cudaGetSymbolAddress((void**)&mhi,  g_mhi);
    cudaGetSymbolAddress((void**)&mlo,  g_mlo);
    cudaGetSymbolAddress((void**)&wqkvth, g_wqkvth);
    cudaGetSymbolAddress((void**)&wqkvtl, g_wqkvtl);
    cudaGetSymbolAddress((void**)&woth, g_woth);
    cudaGetSymbolAddress((void**)&wotl, g_wotl);
    cudaGetSymbolAddress((void**)&w1th, g_w1th);
    cudaGetSymbolAddress((void**)&w1tl, g_w1tl);
    cudaGetSymbolAddress((void**)&w2th, g_w2th);
    cudaGetSymbolAddress((void**)&w2tl, g_w2tl);

    cudaFuncSetAttribute(gemm_mma<0>, cudaFuncAttributeMaxDynamicSharedMemorySize, GSMEM_BYTES);
    cudaFuncSetAttribute(gemm_mma<2>, cudaFuncAttributeMaxDynamicSharedMemorySize, GSMEM_BYTES);
    cudaFuncSetAttribute(gemm_mma<3>, cudaFuncAttributeMaxDynamicSharedMemorySize, GSMEM_BYTES);
    cudaFuncSetAttribute(flash_kernel, cudaFuncAttributeMaxDynamicSharedMemorySize, FSMEM);

    dim3 tb(32, 8);

    // 0: h1 = LN(x) -> hi/lo
    ln_split_kernel<<<MM, 256>>>(x, ln1g, ln1b, ahi, alo);
    // 1: bias concat
    concat3_kernel<<<12, 256>>>(bq, bk, bv, bqkv);
    // 2: ALL weight transposes in one launch
    transpose_all_kernel<<<6144, tb>>>(wq, wk, wv, wo, w1, w2,
        wqkvth, wqkvtl, woth, wotl, w1th, w1tl, w2th, w2tl);

    // 3: fused QKV projection -> q/k/v hi/lo (Q pre-scaled by 1/8)
    dim3 gqkv(3*DD/128, MM/128);
    gemm_mma<3><<<gqkv, 256, GSMEM_BYTES>>>(ahi, alo, wqkvth, wqkvtl, bqkv, nullptr,
        nullptr, qhi, qlo, khi, klo, vhi, vlo, 3*DD, DD);

    // 4: fused flash attention -> ctx hi/lo (reuse ahi/alo)
    flash_kernel<<<dim3(SS/128, BB*HH), 256, FSMEM>>>(
        qhi, qlo, khi, klo, vhi, vlo, ahi, alo);

    // 5: x2 = x + ctx @ wo + bo  (fp32 out)
    dim3 g1(DD/128, MM/128);
    gemm_mma<0><<<g1, 256, GSMEM_BYTES>>>(ahi, alo, woth, wotl, bo, x,
        x2, nullptr, nullptr, nullptr, nullptr, nullptr, nullptr, DD, DD);

    // 6: h2 = LN(x2) -> hi/lo (reuse qhi/qlo)
    ln_split_kernel<<<MM, 256>>>(x2, ln2g, ln2b, qhi, qlo);

    // 7: mlp = gelu(h2 @ w1 + b1) -> hi/lo
    dim3 g2(DFF/128, MM/128);
    gemm_mma<2><<<g2, 256, GSMEM_BYTES>>>(qhi, qlo, w1th, w1tl, b1, nullptr,
        nullptr, mhi, mlo, nullptr, nullptr, nullptr, nullptr, DFF, DD);

    // 8: out = x2 + mlp @ w2 + b2
    gemm_mma<0><<<g1, 256, GSMEM_BYTES>>>(mhi, mlo, w2th, w2tl, b2, x2,
        out, nullptr, nullptr, nullptr, nullptr, nullptr, nullptr, DD, DFF);
}